// round 1
// baseline (speedup 1.0000x reference)
#include <cuda_runtime.h>
#include <math.h>

#define NF 32
#define Dm 256
#define Hh 128
#define Bb 16
#define Tt 512
#define BT (Bb*Tt)      // 8192 positions
#define MT 64           // positions per CTA in pass1
#define DC 64           // D chunk in pass1

// ---- scratch (device globals; no runtime allocation allowed) ----
__device__ float g_stacked[(size_t)BT*NF*Dm];   // 268 MB: post-LN stacked (B,T,F,D)
__device__ float g_pooled[Bb*NF*Dm];            // sum over T
__device__ float g_weights[Bb*NF];

typedef unsigned long long ull;

__device__ __forceinline__ ull pack2(float lo, float hi){
    ull r; asm("mov.b64 %0, {%1, %2};" : "=l"(r) : "f"(lo), "f"(hi)); return r;
}
__device__ __forceinline__ void unpack2(ull v, float &lo, float &hi){
    asm("mov.b64 {%0, %1}, %2;" : "=f"(lo), "=f"(hi) : "l"(v));
}
// packed dual-fp32 FMA (sm_100+): d = a*b + d
__device__ __forceinline__ void ffma2(ull &d, ull a, ull b){
    asm("fma.rn.f32x2 %0, %1, %2, %0;" : "+l"(d) : "l"(a), "l"(b));
}
__device__ __forceinline__ float eluf(float z){ return z > 0.f ? z : expm1f(z); }
__device__ __forceinline__ float sigmoidf_(float z){ return 1.f/(1.f + expf(-z)); }

// ---------------------------------------------------------------------------
// Pass 0: zero the pooled accumulator (graph replays require re-zeroing)
// ---------------------------------------------------------------------------
__global__ void vsn_zero_pooled(){
    int i = blockIdx.x*256 + threadIdx.x;
    if (i < Bb*NF*Dm) g_pooled[i] = 0.f;
}

// ---------------------------------------------------------------------------
// Pass 1: per-feature GRN + LayerNorm, write stacked, accumulate pooled sums.
// grid = (NF, BT/MT), 256 threads, ~168 KB dynamic smem, 1 CTA/SM.
// Thread tile: 4 m x 4 d, dual accumulators (proj, gate) as f32x2 pairs.
// ---------------------------------------------------------------------------
extern __shared__ float smem1[];

__global__ void __launch_bounds__(256,1) vsn_pass1(
    const float* __restrict__ x,  const float* __restrict__ w1, const float* __restrict__ b1,
    const float* __restrict__ w2, const float* __restrict__ b2,
    const float* __restrict__ wg, const float* __restrict__ bg,
    const float* __restrict__ ws, const float* __restrict__ bs,
    const float* __restrict__ lng,const float* __restrict__ lnb)
{
    float* h_s  = smem1;            // [128][64]   8192
    float* w2_s = h_s  + 8192;      // [128][64]   8192
    float* wg_s = w2_s + 8192;      // [128][64]   8192
    float* y_s  = wg_s + 8192;      // [64][256]  16384
    float* b2_s = y_s + 16384;      // 256
    float* bg_s = b2_s + 256;       // 256
    float* ws_s = bg_s + 256;       // 256
    float* bs_s = ws_s + 256;       // 256
    float* lng_s= bs_s + 256;       // 256
    float* lnb_s= lng_s + 256;      // 256
    float* w1_s = lnb_s + 256;      // 128
    float* b1_s = w1_s + 128;       // 128
    float* x_s  = b1_s + 128;       // 64
    float* mu_s = x_s + 64;         // 64
    float* rs_s = mu_s + 64;        // 64

    const int f     = blockIdx.x;       // feature
    const int pbase = blockIdx.y * MT;  // flattened (b,t) base
    const int b     = pbase / Tt;
    const int tid   = threadIdx.x;
    const int tx    = tid & 15;         // -> d group
    const int ty    = tid >> 4;         // -> m group

    // ---- stage params ----
    if (tid < 64)  x_s[tid] = x[(size_t)(pbase + tid)*NF + f];
    if (tid < 128){ w1_s[tid] = w1[f*Hh + tid]; b1_s[tid] = b1[f*Hh + tid]; }
    b2_s[tid] = b2[f*Dm + tid];  bg_s[tid] = bg[f*Dm + tid];
    ws_s[tid] = ws[f*Dm + tid];  bs_s[tid] = bs[f*Dm + tid];
    lng_s[tid]= lng[f*Dm + tid]; lnb_s[tid]= lnb[f*Dm + tid];
    __syncthreads();

    // ---- h[j][m] = elu(x[m]*w1[j] + b1[j]) ----
    #pragma unroll
    for (int i = 0; i < 32; i++){
        int idx = tid + i*256;
        int j = idx >> 6, m = idx & 63;
        h_s[idx] = eluf(fmaf(x_s[m], w1_s[j], b1_s[j]));
    }
    __syncthreads();

    // ---- D chunks of 64: dual GEMM (proj, gate) + fused epilogue into y_s ----
    for (int c = 0; c < 4; c++){
        const int dbase = c * DC;
        // stage weight chunks
        {
            int j0 = tid >> 4, d4 = (tid & 15) * 4;
            #pragma unroll
            for (int p = 0; p < 8; p++){
                int j = j0 + p*16;
                size_t goff = ((size_t)(f*Hh + j))*Dm + dbase + d4;
                *(float4*)(w2_s + j*64 + d4) = *(const float4*)(w2 + goff);
                *(float4*)(wg_s + j*64 + d4) = *(const float4*)(wg + goff);
            }
        }
        __syncthreads();

        ull ap[4][2], ag[4][2];
        #pragma unroll
        for (int i = 0; i < 4; i++){ ap[i][0]=ap[i][1]=ag[i][0]=ag[i][1]=0ULL; }

        #pragma unroll 4
        for (int j = 0; j < 128; j++){
            float4 h4 = *(const float4*)(h_s + j*64 + ty*4);
            ull hx0 = pack2(h4.x, h4.x), hx1 = pack2(h4.y, h4.y);
            ull hx2 = pack2(h4.z, h4.z), hx3 = pack2(h4.w, h4.w);
            ulonglong2 wp = *(const ulonglong2*)(w2_s + j*64 + tx*4);
            ulonglong2 wq = *(const ulonglong2*)(wg_s + j*64 + tx*4);
            ffma2(ap[0][0], hx0, wp.x); ffma2(ap[0][1], hx0, wp.y);
            ffma2(ag[0][0], hx0, wq.x); ffma2(ag[0][1], hx0, wq.y);
            ffma2(ap[1][0], hx1, wp.x); ffma2(ap[1][1], hx1, wp.y);
            ffma2(ag[1][0], hx1, wq.x); ffma2(ag[1][1], hx1, wq.y);
            ffma2(ap[2][0], hx2, wp.x); ffma2(ap[2][1], hx2, wp.y);
            ffma2(ag[2][0], hx2, wq.x); ffma2(ag[2][1], hx2, wq.y);
            ffma2(ap[3][0], hx3, wp.x); ffma2(ap[3][1], hx3, wp.y);
            ffma2(ag[3][0], hx3, wq.x); ffma2(ag[3][1], hx3, wq.y);
        }

        // epilogue: y = skip + sigmoid(gate)*proj (pre-LN)
        #pragma unroll
        for (int i = 0; i < 4; i++){
            int m = ty*4 + i;
            float xm = x_s[m];
            int d0 = dbase + tx*4;
            float p0,p1,p2,p3,g0,g1,g2,g3;
            unpack2(ap[i][0], p0, p1); unpack2(ap[i][1], p2, p3);
            unpack2(ag[i][0], g0, g1); unpack2(ag[i][1], g2, g3);
            float4 yv;
            yv.x = fmaf(xm, ws_s[d0+0], bs_s[d0+0]) + sigmoidf_(g0 + bg_s[d0+0]) * (p0 + b2_s[d0+0]);
            yv.y = fmaf(xm, ws_s[d0+1], bs_s[d0+1]) + sigmoidf_(g1 + bg_s[d0+1]) * (p1 + b2_s[d0+1]);
            yv.z = fmaf(xm, ws_s[d0+2], bs_s[d0+2]) + sigmoidf_(g2 + bg_s[d0+2]) * (p2 + b2_s[d0+2]);
            yv.w = fmaf(xm, ws_s[d0+3], bs_s[d0+3]) + sigmoidf_(g3 + bg_s[d0+3]) * (p3 + b2_s[d0+3]);
            *(float4*)(y_s + m*256 + d0) = yv;
        }
        __syncthreads();   // protect w2_s/wg_s for next chunk + y_s for stats
    }

    // ---- LayerNorm stats over D=256 (4 lanes per row) ----
    {
        int m = tid >> 2, q = tid & 3;
        float s = 0.f, ss = 0.f;
        const float* yr = y_s + m*256 + q*64;
        #pragma unroll
        for (int k = 0; k < 64; k++){ float v = yr[k]; s += v; ss = fmaf(v, v, ss); }
        s  += __shfl_xor_sync(0xffffffffu, s, 1);  ss += __shfl_xor_sync(0xffffffffu, ss, 1);
        s  += __shfl_xor_sync(0xffffffffu, s, 2);  ss += __shfl_xor_sync(0xffffffffu, ss, 2);
        if (q == 0){
            float mu = s * (1.f/256.f);
            float var = ss * (1.f/256.f) - mu*mu;
            mu_s[m] = mu; rs_s[m] = rsqrtf(var + 1e-5f);
        }
    }
    __syncthreads();

    // ---- normalize, write stacked, accumulate pooled ----
    {
        int d = tid;
        float lg = lng_s[d], lb = lnb_s[d];
        float psum = 0.f;
        float* ob = g_stacked + ((size_t)pbase*NF + f)*Dm + d;
        #pragma unroll 4
        for (int m = 0; m < 64; m++){
            float v = fmaf((y_s[m*256 + d] - mu_s[m]) * rs_s[m], lg, lb);
            ob[(size_t)m*NF*Dm] = v;
            psum += v;
        }
        atomicAdd(&g_pooled[((size_t)b*NF + f)*Dm + d], psum);
    }
}

// ---------------------------------------------------------------------------
// Pass 2: weight GRN + softmax. grid = B, 256 threads.
// ---------------------------------------------------------------------------
__global__ void __launch_bounds__(256,1) vsn_pass2(
    const float* __restrict__ W1, const float* __restrict__ B1,
    const float* __restrict__ W2, const float* __restrict__ B2,
    const float* __restrict__ Wg, const float* __restrict__ Bg,
    const float* __restrict__ Ws, const float* __restrict__ Bs,
    const float* __restrict__ LNg,const float* __restrict__ LNb,
    float* wout)
{
    __shared__ float fp_s[NF*Dm];        // 8192 flat pooled features
    __shared__ float hw_s[Dm];
    __shared__ float part[3][8][NF];

    const int b = blockIdx.x, tid = threadIdx.x;
    const int k = tid & 31, pt = tid >> 5;

    for (int i = tid; i < NF*Dm; i += 256)
        fp_s[i] = g_pooled[(size_t)b*NF*Dm + i] * (1.f/(float)Tt);
    __syncthreads();

    // hw[d] = elu(fp @ W1 + B1), one thread per d
    {
        float acc = B1[tid];
        const float* wc = W1 + tid;
        #pragma unroll 4
        for (int i = 0; i < NF*Dm; i++)
            acc = fmaf(fp_s[i], wc[(size_t)i*Dm], acc);
        hw_s[tid] = eluf(acc);
    }
    // skip partials: sk[k] = fp @ Ws (8 partitions over i)
    {
        float acc = 0.f;
        const float* wc = Ws + k;
        int i0 = pt * 1024;
        #pragma unroll 4
        for (int i = i0; i < i0 + 1024; i++)
            acc = fmaf(fp_s[i], wc[(size_t)i*NF], acc);
        part[0][pt][k] = acc;
    }
    __syncthreads();
    // pw/gw partials over d
    {
        float a2 = 0.f, a3 = 0.f;
        int d0 = pt * 32;
        #pragma unroll
        for (int d = d0; d < d0 + 32; d++){
            float h = hw_s[d];
            a2 = fmaf(h, W2[d*NF + k], a2);
            a3 = fmaf(h, Wg[d*NF + k], a3);
        }
        part[1][pt][k] = a2; part[2][pt][k] = a3;
    }
    __syncthreads();

    if (tid < 32){
        float sk = Bs[k], pw = B2[k], gw = Bg[k];
        #pragma unroll
        for (int p = 0; p < 8; p++){ sk += part[0][p][k]; pw += part[1][p][k]; gw += part[2][p][k]; }
        float v = sk + sigmoidf_(gw) * pw;
        // LN over 32 features
        float s = v, ss = v*v;
        #pragma unroll
        for (int o = 16; o > 0; o >>= 1){
            s  += __shfl_xor_sync(0xffffffffu, s, o);
            ss += __shfl_xor_sync(0xffffffffu, ss, o);
        }
        float mu = s * (1.f/32.f);
        float var = ss * (1.f/32.f) - mu*mu;
        float y = fmaf((v - mu) * rsqrtf(var + 1e-5f), LNg[k], LNb[k]);
        // softmax
        float mx = y;
        #pragma unroll
        for (int o = 16; o > 0; o >>= 1) mx = fmaxf(mx, __shfl_xor_sync(0xffffffffu, mx, o));
        float e = expf(y - mx);
        float se = e;
        #pragma unroll
        for (int o = 16; o > 0; o >>= 1) se += __shfl_xor_sync(0xffffffffu, se, o);
        float w = e / se;
        g_weights[b*NF + k] = w;
        if (wout) wout[b*NF + k] = w;
    }
}

// ---------------------------------------------------------------------------
// Pass 3: selected[b,t,:] = sum_f stacked[b,t,f,:] * weights[b,f]
// grid = B*T, 256 threads (one per d)
// ---------------------------------------------------------------------------
__global__ void __launch_bounds__(256,1) vsn_pass3(float* __restrict__ out)
{
    __shared__ float w_s[NF];
    const int p = blockIdx.x;
    const int b = p >> 9;            // / Tt
    const int tid = threadIdx.x;
    if (tid < NF) w_s[tid] = g_weights[b*NF + tid];
    __syncthreads();
    const float* base = g_stacked + (size_t)p*NF*Dm + tid;
    float acc = 0.f;
    #pragma unroll
    for (int f2 = 0; f2 < NF; f2++)
        acc = fmaf(base[(size_t)f2*Dm], w_s[f2], acc);
    out[(size_t)p*Dm + tid] = acc;
}

// ---------------------------------------------------------------------------
extern "C" void kernel_launch(void* const* d_in, const int* in_sizes, int n_in,
                              void* d_out, int out_size)
{
    const float* x   = (const float*)d_in[0];
    const float* w1  = (const float*)d_in[1];
    const float* b1  = (const float*)d_in[2];
    const float* w2  = (const float*)d_in[3];
    const float* b2  = (const float*)d_in[4];
    const float* wg  = (const float*)d_in[5];
    const float* bg  = (const float*)d_in[6];
    const float* ws  = (const float*)d_in[7];
    const float* bs  = (const float*)d_in[8];
    const float* lng = (const float*)d_in[9];
    const float* lnb = (const float*)d_in[10];
    const float* W1  = (const float*)d_in[11];
    const float* B1  = (const float*)d_in[12];
    const float* W2  = (const float*)d_in[13];
    const float* B2  = (const float*)d_in[14];
    const float* Wg  = (const float*)d_in[15];
    const float* Bg  = (const float*)d_in[16];
    const float* Ws  = (const float*)d_in[17];
    const float* Bs  = (const float*)d_in[18];
    const float* LNg = (const float*)d_in[19];
    const float* LNb = (const float*)d_in[20];

    const int smem1 = (8192*3 + 16384 + 6*256 + 2*128 + 3*64) * 4;  // 171776 B
    cudaFuncSetAttribute(vsn_pass1, cudaFuncAttributeMaxDynamicSharedMemorySize, smem1);

    float* out = (float*)d_out;
    // weights tail only if the harness output is the concatenated tuple
    float* wout = (out_size > BT*Dm) ? out + (size_t)BT*Dm : nullptr;

    vsn_zero_pooled<<<(Bb*NF*Dm + 255)/256, 256>>>();
    dim3 g1(NF, BT/MT);
    vsn_pass1<<<g1, 256, smem1>>>(x, w1, b1, w2, b2, wg, bg, ws, bs, lng, lnb);
    vsn_pass2<<<Bb, 256>>>(W1, B1, W2, B2, Wg, Bg, Ws, Bs, LNg, LNb, wout);
    vsn_pass3<<<BT, 256>>>(out);
}

// round 2
// speedup vs baseline: 1.0774x; 1.0774x over previous
#include <cuda_runtime.h>
#include <math.h>

#define NF 32
#define Dm 256
#define Hh 128
#define Bb 16
#define Tt 512
#define BT (Bb*Tt)      // 8192 positions
#define MT 64           // positions per CTA in pass1
#define DC 128          // D chunk in pass1

// ---- scratch (device globals; no runtime allocation allowed) ----
__device__ float g_stacked[(size_t)BT*NF*Dm];   // 268 MB: post-LN stacked (B,T,F,D)
__device__ float g_pooled[Bb*NF*Dm];            // sum over T
__device__ float g_weights[Bb*NF];

typedef unsigned long long ull;

__device__ __forceinline__ ull pack2(float lo, float hi){
    ull r; asm("mov.b64 %0, {%1, %2};" : "=l"(r) : "f"(lo), "f"(hi)); return r;
}
__device__ __forceinline__ void unpack2(ull v, float &lo, float &hi){
    asm("mov.b64 {%0, %1}, %2;" : "=f"(lo), "=f"(hi) : "l"(v));
}
// packed dual-fp32 FMA (sm_100+): d = a*b + d
__device__ __forceinline__ void ffma2(ull &d, ull a, ull b){
    asm("fma.rn.f32x2 %0, %1, %2, %0;" : "+l"(d) : "l"(a), "l"(b));
}
__device__ __forceinline__ float eluf(float z){ return z > 0.f ? z : expm1f(z); }
__device__ __forceinline__ float sigmoidf_(float z){ return 1.f/(1.f + __expf(-z)); }

// ---------------------------------------------------------------------------
// Pass 0: zero the pooled accumulator (graph replays require re-zeroing)
// ---------------------------------------------------------------------------
__global__ void vsn_zero_pooled(){
    int i = blockIdx.x*256 + threadIdx.x;
    if (i < Bb*NF*Dm) g_pooled[i] = 0.f;
}

// ---------------------------------------------------------------------------
// Pass 1: per-feature GRN + LayerNorm, write stacked, accumulate pooled sums.
// grid = (NF, BT/MT), 256 threads, ~167 KB dynamic smem, 1 CTA/SM.
// Warp layout: tx = lane (32 d-groups), ty = warp (8 m-groups).
// Thread tile: 8 m x 4 d per D-chunk of 128; pre-LN y kept in registers.
// h loads are warp-broadcast LDS; kernel is FMA-pipe bound (f32x2 FFMA).
// ---------------------------------------------------------------------------
extern __shared__ float smem1[];

__global__ void __launch_bounds__(256,1) vsn_pass1(
    const float* __restrict__ x,  const float* __restrict__ w1, const float* __restrict__ b1,
    const float* __restrict__ w2, const float* __restrict__ b2,
    const float* __restrict__ wg, const float* __restrict__ bg,
    const float* __restrict__ ws, const float* __restrict__ bs,
    const float* __restrict__ lng,const float* __restrict__ lnb)
{
    float* h_s  = smem1;             // [128][64]    8192
    float* w2_s = h_s  + 8192;       // [128][128]  16384
    float* wg_s = w2_s + 16384;      // [128][128]  16384
    float* b2_s = wg_s + 16384;      // 256
    float* bg_s = b2_s + 256;
    float* ws_s = bg_s + 256;
    float* bs_s = ws_s + 256;
    float* lng_s= bs_s + 256;
    float* lnb_s= lng_s + 256;
    float* w1_s = lnb_s + 256;       // 128
    float* b1_s = w1_s + 128;        // 128
    float* x_s  = b1_s + 128;        // 64
    // total 42816 floats = 171264 B

    const int f     = blockIdx.x;       // feature
    const int pbase = blockIdx.y * MT;  // flattened (b,t) base
    const int b     = pbase / Tt;
    const int tid   = threadIdx.x;
    const int tx    = tid & 31;         // lane  -> d group (4 floats)
    const int ty    = tid >> 5;         // warp  -> m group (8 rows)

    // ---- stage params ----
    if (tid < 64)  x_s[tid] = x[(size_t)(pbase + tid)*NF + f];
    if (tid < 128){ w1_s[tid] = w1[f*Hh + tid]; b1_s[tid] = b1[f*Hh + tid]; }
    b2_s[tid] = b2[f*Dm + tid];  bg_s[tid] = bg[f*Dm + tid];
    ws_s[tid] = ws[f*Dm + tid];  bs_s[tid] = bs[f*Dm + tid];
    lng_s[tid]= lng[f*Dm + tid]; lnb_s[tid]= lnb[f*Dm + tid];
    __syncthreads();

    // ---- h[j][m] = elu(x[m]*w1[j] + b1[j]) ----
    #pragma unroll
    for (int i = 0; i < 32; i++){
        int idx = tid + i*256;
        int j = idx >> 6, m = idx & 63;
        h_s[idx] = eluf(fmaf(x_s[m], w1_s[j], b1_s[j]));
    }
    __syncthreads();

    float yv[2][8][4];   // pre-LN output: [chunk][m_i][k]

    #pragma unroll
    for (int c = 0; c < 2; c++){
        // ---- stage weight chunk [128][128] for both tensors ----
        {
            int j0 = tid >> 5, c4 = (tid & 31) * 4;
            #pragma unroll
            for (int p = 0; p < 16; p++){
                int j = j0 + p*8;
                size_t goff = ((size_t)(f*Hh + j))*Dm + c*DC + c4;
                *(float4*)(w2_s + j*128 + c4) = *(const float4*)(w2 + goff);
                *(float4*)(wg_s + j*128 + c4) = *(const float4*)(wg + goff);
            }
        }
        __syncthreads();

        ull ap[8][2], ag[8][2];
        #pragma unroll
        for (int i = 0; i < 8; i++){ ap[i][0]=ap[i][1]=ag[i][0]=ag[i][1]=0ULL; }

        #pragma unroll 2
        for (int j = 0; j < 128; j++){
            float4 ha = *(const float4*)(h_s + j*64 + ty*8);      // broadcast
            float4 hb = *(const float4*)(h_s + j*64 + ty*8 + 4);  // broadcast
            ulonglong2 wp = *(const ulonglong2*)(w2_s + j*128 + tx*4);
            ulonglong2 wq = *(const ulonglong2*)(wg_s + j*128 + tx*4);
            float hv[8] = {ha.x,ha.y,ha.z,ha.w,hb.x,hb.y,hb.z,hb.w};
            #pragma unroll
            for (int i = 0; i < 8; i++){
                ull hx = pack2(hv[i], hv[i]);
                ffma2(ap[i][0], hx, wp.x); ffma2(ap[i][1], hx, wp.y);
                ffma2(ag[i][0], hx, wq.x); ffma2(ag[i][1], hx, wq.y);
            }
        }

        // ---- epilogue: y = skip + sigmoid(gate)*proj (pre-LN), into regs ----
        {
            float4 b2v = *(const float4*)(b2_s + c*DC + tx*4);
            float4 bgv = *(const float4*)(bg_s + c*DC + tx*4);
            float4 wsv = *(const float4*)(ws_s + c*DC + tx*4);
            float4 bsv = *(const float4*)(bs_s + c*DC + tx*4);
            #pragma unroll
            for (int i = 0; i < 8; i++){
                float xm = x_s[ty*8 + i];
                float p0,p1,p2,p3,g0,g1,g2,g3;
                unpack2(ap[i][0], p0, p1); unpack2(ap[i][1], p2, p3);
                unpack2(ag[i][0], g0, g1); unpack2(ag[i][1], g2, g3);
                yv[c][i][0] = fmaf(xm, wsv.x, bsv.x) + sigmoidf_(g0 + bgv.x) * (p0 + b2v.x);
                yv[c][i][1] = fmaf(xm, wsv.y, bsv.y) + sigmoidf_(g1 + bgv.y) * (p1 + b2v.y);
                yv[c][i][2] = fmaf(xm, wsv.z, bsv.z) + sigmoidf_(g2 + bgv.z) * (p2 + b2v.z);
                yv[c][i][3] = fmaf(xm, wsv.w, bsv.w) + sigmoidf_(g3 + bgv.w) * (p3 + b2v.w);
            }
        }
        __syncthreads();   // weights buffer reused next chunk
    }

    // ---- LayerNorm stats: each row m lives entirely in one warp ----
    float mu[8], rs[8];
    #pragma unroll
    for (int i = 0; i < 8; i++){
        float s = 0.f, ss = 0.f;
        #pragma unroll
        for (int c = 0; c < 2; c++)
            #pragma unroll
            for (int k = 0; k < 4; k++){ float v = yv[c][i][k]; s += v; ss = fmaf(v, v, ss); }
        #pragma unroll
        for (int o = 16; o > 0; o >>= 1){
            s  += __shfl_xor_sync(0xffffffffu, s, o);
            ss += __shfl_xor_sync(0xffffffffu, ss, o);
        }
        float m_ = s * (1.f/256.f);
        float var = ss * (1.f/256.f) - m_*m_;
        mu[i] = m_; rs[i] = rsqrtf(var + 1e-5f);
    }

    // ---- normalize, write stacked, accumulate pooled (regs -> smem -> atomic) ----
    float4 lg0 = *(const float4*)(lng_s + tx*4),       lb0 = *(const float4*)(lnb_s + tx*4);
    float4 lg1 = *(const float4*)(lng_s + 128 + tx*4), lb1 = *(const float4*)(lnb_s + 128 + tx*4);
    float4 ps0 = make_float4(0.f,0.f,0.f,0.f), ps1 = ps0;
    #pragma unroll
    for (int i = 0; i < 8; i++){
        float* row = g_stacked + ((size_t)(pbase + ty*8 + i)*NF + f)*Dm;
        float4 o0, o1;
        o0.x = fmaf((yv[0][i][0]-mu[i])*rs[i], lg0.x, lb0.x);
        o0.y = fmaf((yv[0][i][1]-mu[i])*rs[i], lg0.y, lb0.y);
        o0.z = fmaf((yv[0][i][2]-mu[i])*rs[i], lg0.z, lb0.z);
        o0.w = fmaf((yv[0][i][3]-mu[i])*rs[i], lg0.w, lb0.w);
        o1.x = fmaf((yv[1][i][0]-mu[i])*rs[i], lg1.x, lb1.x);
        o1.y = fmaf((yv[1][i][1]-mu[i])*rs[i], lg1.y, lb1.y);
        o1.z = fmaf((yv[1][i][2]-mu[i])*rs[i], lg1.z, lb1.z);
        o1.w = fmaf((yv[1][i][3]-mu[i])*rs[i], lg1.w, lb1.w);
        *(float4*)(row + tx*4)       = o0;
        *(float4*)(row + 128 + tx*4) = o1;
        ps0.x += o0.x; ps0.y += o0.y; ps0.z += o0.z; ps0.w += o0.w;
        ps1.x += o1.x; ps1.y += o1.y; ps1.z += o1.z; ps1.w += o1.w;
    }

    // reduce pooled partials across the 8 warps via smem (reuse h_s region)
    __syncthreads();
    float* ps_s = h_s;  // [8 warps][256 d]
    *(float4*)(ps_s + ty*256 + tx*4)       = ps0;
    *(float4*)(ps_s + ty*256 + 128 + tx*4) = ps1;
    __syncthreads();
    {
        int d = tid;
        float s = 0.f;
        #pragma unroll
        for (int w = 0; w < 8; w++) s += ps_s[w*256 + d];
        atomicAdd(&g_pooled[((size_t)b*NF + f)*Dm + d], s);
    }
}

// ---------------------------------------------------------------------------
// Pass 2: weight GRN + softmax. grid = B, 256 threads.
// ---------------------------------------------------------------------------
__global__ void __launch_bounds__(256,1) vsn_pass2(
    const float* __restrict__ W1, const float* __restrict__ B1,
    const float* __restrict__ W2, const float* __restrict__ B2,
    const float* __restrict__ Wg, const float* __restrict__ Bg,
    const float* __restrict__ Ws, const float* __restrict__ Bs,
    const float* __restrict__ LNg,const float* __restrict__ LNb,
    float* wout)
{
    __shared__ float fp_s[NF*Dm];        // 8192 flat pooled features
    __shared__ float hw_s[Dm];
    __shared__ float part[3][8][NF];

    const int b = blockIdx.x, tid = threadIdx.x;
    const int k = tid & 31, pt = tid >> 5;

    for (int i = tid; i < NF*Dm; i += 256)
        fp_s[i] = g_pooled[(size_t)b*NF*Dm + i] * (1.f/(float)Tt);
    __syncthreads();

    // hw[d] = elu(fp @ W1 + B1), one thread per d
    {
        float acc = B1[tid];
        const float* wc = W1 + tid;
        #pragma unroll 4
        for (int i = 0; i < NF*Dm; i++)
            acc = fmaf(fp_s[i], wc[(size_t)i*Dm], acc);
        hw_s[tid] = eluf(acc);
    }
    // skip partials: sk[k] = fp @ Ws (8 partitions over i)
    {
        float acc = 0.f;
        const float* wc = Ws + k;
        int i0 = pt * 1024;
        #pragma unroll 4
        for (int i = i0; i < i0 + 1024; i++)
            acc = fmaf(fp_s[i], wc[(size_t)i*NF], acc);
        part[0][pt][k] = acc;
    }
    __syncthreads();
    // pw/gw partials over d
    {
        float a2 = 0.f, a3 = 0.f;
        int d0 = pt * 32;
        #pragma unroll
        for (int d = d0; d < d0 + 32; d++){
            float h = hw_s[d];
            a2 = fmaf(h, W2[d*NF + k], a2);
            a3 = fmaf(h, Wg[d*NF + k], a3);
        }
        part[1][pt][k] = a2; part[2][pt][k] = a3;
    }
    __syncthreads();

    if (tid < 32){
        float sk = Bs[k], pw = B2[k], gw = Bg[k];
        #pragma unroll
        for (int p = 0; p < 8; p++){ sk += part[0][p][k]; pw += part[1][p][k]; gw += part[2][p][k]; }
        float v = sk + sigmoidf_(gw) * pw;
        // LN over 32 features
        float s = v, ss = v*v;
        #pragma unroll
        for (int o = 16; o > 0; o >>= 1){
            s  += __shfl_xor_sync(0xffffffffu, s, o);
            ss += __shfl_xor_sync(0xffffffffu, ss, o);
        }
        float mu = s * (1.f/32.f);
        float var = ss * (1.f/32.f) - mu*mu;
        float y = fmaf((v - mu) * rsqrtf(var + 1e-5f), LNg[k], LNb[k]);
        // softmax
        float mx = y;
        #pragma unroll
        for (int o = 16; o > 0; o >>= 1) mx = fmaxf(mx, __shfl_xor_sync(0xffffffffu, mx, o));
        float e = expf(y - mx);
        float se = e;
        #pragma unroll
        for (int o = 16; o > 0; o >>= 1) se += __shfl_xor_sync(0xffffffffu, se, o);
        float w = e / se;
        g_weights[b*NF + k] = w;
        if (wout) wout[b*NF + k] = w;
    }
}

// ---------------------------------------------------------------------------
// Pass 3: selected[b,t,:] = sum_f stacked[b,t,f,:] * weights[b,f]
// grid = B*T, 256 threads (one per d) — at DRAM roofline already.
// ---------------------------------------------------------------------------
__global__ void __launch_bounds__(256,1) vsn_pass3(float* __restrict__ out)
{
    __shared__ float w_s[NF];
    const int p = blockIdx.x;
    const int b = p >> 9;            // / Tt
    const int tid = threadIdx.x;
    if (tid < NF) w_s[tid] = g_weights[b*NF + tid];
    __syncthreads();
    const float* base = g_stacked + (size_t)p*NF*Dm + tid;
    float acc = 0.f;
    #pragma unroll
    for (int f2 = 0; f2 < NF; f2++)
        acc = fmaf(base[(size_t)f2*Dm], w_s[f2], acc);
    out[(size_t)p*Dm + tid] = acc;
}

// ---------------------------------------------------------------------------
extern "C" void kernel_launch(void* const* d_in, const int* in_sizes, int n_in,
                              void* d_out, int out_size)
{
    const float* x   = (const float*)d_in[0];
    const float* w1  = (const float*)d_in[1];
    const float* b1  = (const float*)d_in[2];
    const float* w2  = (const float*)d_in[3];
    const float* b2  = (const float*)d_in[4];
    const float* wg  = (const float*)d_in[5];
    const float* bg  = (const float*)d_in[6];
    const float* ws  = (const float*)d_in[7];
    const float* bs  = (const float*)d_in[8];
    const float* lng = (const float*)d_in[9];
    const float* lnb = (const float*)d_in[10];
    const float* W1  = (const float*)d_in[11];
    const float* B1  = (const float*)d_in[12];
    const float* W2  = (const float*)d_in[13];
    const float* B2  = (const float*)d_in[14];
    const float* Wg  = (const float*)d_in[15];
    const float* Bg  = (const float*)d_in[16];
    const float* Ws  = (const float*)d_in[17];
    const float* Bs  = (const float*)d_in[18];
    const float* LNg = (const float*)d_in[19];
    const float* LNb = (const float*)d_in[20];

    const int smem1 = (8192 + 16384*2 + 6*256 + 2*128 + 64) * 4;  // 171264 B
    cudaFuncSetAttribute(vsn_pass1, cudaFuncAttributeMaxDynamicSharedMemorySize, smem1);

    float* out = (float*)d_out;
    float* wout = (out_size > BT*Dm) ? out + (size_t)BT*Dm : nullptr;

    vsn_zero_pooled<<<(Bb*NF*Dm + 255)/256, 256>>>();
    dim3 g1(NF, BT/MT);
    vsn_pass1<<<g1, 256, smem1>>>(x, w1, b1, w2, b2, wg, bg, ws, bs, lng, lnb);
    vsn_pass2<<<Bb, 256>>>(W1, B1, W2, B2, Wg, Bg, Ws, Bs, LNg, LNb, wout);
    vsn_pass3<<<BT, 256>>>(out);
}

// round 4
// speedup vs baseline: 1.1044x; 1.0251x over previous
#include <cuda_runtime.h>
#include <cuda_bf16.h>
#include <math.h>
#include <stdint.h>

#define NF 32
#define Dm 256
#define Hh 128
#define Bb 16
#define Tt 512
#define BT (Bb*Tt)      // 8192 positions
#define MT 64           // positions per CTA in pass1
#define PW 136          // bf16 pitch (elems) of prepped weight / h tiles
#define PWB 272         // bytes
#define PA 133          // fp32 pitch of accum overlay

// ---------------- scratch (device globals; no runtime allocation) ----------
__device__ float g_stacked[(size_t)BT*NF*Dm];   // 268 MB post-LN stacked (B,T,F,D)
__device__ float g_pooledA[Bb*NF*Dm];           // sum_t rs_t * y[t,d]
__device__ float g_pooledB[Bb*NF];              // sum_t rs_t * mu_t
__device__ float g_weights[Bb*NF];
// prepped weights: [f][tensor][part][d=256][k pitch 136] bf16  (part: 0=hi,1=lo)
__device__ __nv_bfloat16 g_wprep[128 * 256 * PW];   // 8.9 MB

// ---------------- helpers --------------------------------------------------
__device__ __forceinline__ uint32_t smem_u32(const void* p){
    uint32_t a;
    asm("{ .reg .u64 t; cvta.to.shared.u64 t, %1; cvt.u32.u64 %0, t; }" : "=r"(a) : "l"(p));
    return a;
}
__device__ __forceinline__ void ldsm_x4(uint32_t (&r)[4], uint32_t a){
    asm volatile("ldmatrix.sync.aligned.m8n8.x4.shared.b16 {%0,%1,%2,%3}, [%4];"
        : "=r"(r[0]),"=r"(r[1]),"=r"(r[2]),"=r"(r[3]) : "r"(a));
}
__device__ __forceinline__ void ldsm_x2(uint32_t (&r)[2], uint32_t a){
    asm volatile("ldmatrix.sync.aligned.m8n8.x2.shared.b16 {%0,%1}, [%2];"
        : "=r"(r[0]),"=r"(r[1]) : "r"(a));
}
__device__ __forceinline__ void mma16816(float (&c)[4], const uint32_t (&a)[4], const uint32_t (&b)[2]){
    asm volatile("mma.sync.aligned.m16n8k16.row.col.f32.bf16.bf16.f32 "
        "{%0,%1,%2,%3}, {%4,%5,%6,%7}, {%8,%9}, {%0,%1,%2,%3};"
        : "+f"(c[0]),"+f"(c[1]),"+f"(c[2]),"+f"(c[3])
        : "r"(a[0]),"r"(a[1]),"r"(a[2]),"r"(a[3]), "r"(b[0]),"r"(b[1]));
}
__device__ __forceinline__ float eluf(float z){ return z > 0.f ? z : expm1f(z); }
__device__ __forceinline__ float sigf(float z){ return __fdividef(1.f, 1.f + __expf(-z)); }

// ---------------------------------------------------------------------------
// Prep: w2/wg -> bf16 hi/lo, transposed to [d][k] pitch-136 images.
// grid = 128 (f*4 + t*2 + p), 256 threads.
// ---------------------------------------------------------------------------
__global__ void __launch_bounds__(256,1) vsn_prep(const float* __restrict__ w2,
                                                  const float* __restrict__ wg)
{
    __shared__ float ts[128][65];   // [k][d-chunk 64] staging transpose
    const int bid = blockIdx.x;
    const int f = bid >> 2, t = (bid >> 1) & 1, p = bid & 1;
    const int tid = threadIdx.x;
    const float* W = (t ? wg : w2) + (size_t)f*Hh*Dm;       // [k][d], k<128, d<256
    __nv_bfloat16* dst = g_wprep + (size_t)bid * 256 * PW;  // [d][k pitch 136]

    for (int dc = 0; dc < 4; dc++){
        #pragma unroll
        for (int i = 0; i < 32; i++){
            int e = tid + i*256;
            int d = e & 63, k = e >> 6;
            ts[k][d] = W[(size_t)k*Dm + dc*64 + d];
        }
        __syncthreads();
        #pragma unroll
        for (int i = 0; i < 4; i++){
            int g = tid + i*256;
            int d = g >> 4, kg = g & 15;
            union { __nv_bfloat16 h[8]; uint4 v; } o;
            #pragma unroll
            for (int j = 0; j < 8; j++){
                float v = ts[kg*8 + j][d];
                __nv_bfloat16 hi = __float2bfloat16(v);
                o.h[j] = p ? __float2bfloat16(v - __bfloat162float(hi)) : hi;
            }
            *(uint4*)(dst + (size_t)(dc*64 + d)*PW + kg*8) = o.v;
        }
        __syncthreads();
    }
}

// ---------------------------------------------------------------------------
// Zero pooled accumulators (graph replays need fresh zeros)
// ---------------------------------------------------------------------------
__global__ void vsn_zero(){
    int i = blockIdx.x*256 + threadIdx.x;
    if (i < Bb*NF*Dm) g_pooledA[i] = 0.f;
    if (i < Bb*NF)    g_pooledB[i] = 0.f;
}

// ---------------------------------------------------------------------------
// Pass 1 (mma.sync bf16, 3-term split): per-feature GRN + LN + stacked + pooled
// grid = (NF, BT/MT) = (32,128), 256 threads, 189472 B dyn smem (1 CTA/SM).
// Warps 0-3: proj (d-quarters), warps 4-7: gate.
// ---------------------------------------------------------------------------
#define OFF_HHI 0
#define OFF_HLO 17408
#define OFF_WT  34816
#define OFF_PAR 174080
#define SMEM1_BYTES (174080 + 15392)

extern __shared__ char sm1[];

__global__ void __launch_bounds__(256,1) vsn_pass1(
    const float* __restrict__ x,  const float* __restrict__ w1, const float* __restrict__ b1,
    const float* __restrict__ b2, const float* __restrict__ bg,
    const float* __restrict__ ws, const float* __restrict__ bs,
    const float* __restrict__ lng,const float* __restrict__ lnb)
{
    const int f     = blockIdx.x;
    const int pbase = blockIdx.y * MT;
    const int b     = pbase / Tt;
    const int tid   = threadIdx.x;
    const int lane  = tid & 31;
    const int wid   = tid >> 5;
    const int r     = tid >> 2;       // row 0..63
    const int dq    = tid & 3;        // d-quarter within chunk

    char* HHI = sm1 + OFF_HHI;       // [64][136] bf16 hi
    char* HLO = sm1 + OFF_HLO;
    char* WT  = sm1 + OFF_WT;        // 4 x [128][136] bf16 tiles / accum overlay
    float* b2_s = (float*)(sm1 + OFF_PAR);
    float* bg_s = b2_s + 256;
    float* ws_s = bg_s + 256;
    float* bs_s = ws_s + 256;
    float* lng_s= bs_s + 256;
    float* lnb_s= lng_s + 256;
    float* w1_s = lnb_s + 256;       // 128
    float* b1_s = w1_s + 128;        // 128
    float* poolw= b1_s + 128;        // [8][256]
    float* poolb= poolw + 2048;      // [8]

    // ---- stage params ----
    b2_s[tid] = b2[f*Dm + tid];
    bg_s[tid] = bg[f*Dm + tid];
    ws_s[tid] = ws[f*Dm + tid];
    bs_s[tid] = bs[f*Dm + tid];
    lng_s[tid]= lng[f*Dm + tid];
    lnb_s[tid]= lnb[f*Dm + tid];
    if (tid < 128){ w1_s[tid] = w1[f*Hh + tid]; b1_s[tid] = b1[f*Hh + tid]; }
    const float x_r = x[(size_t)(pbase + r)*NF + f];
    __syncthreads();

    // ---- h[r][k] = elu(x_r*w1[k]+b1[k]), bf16 hi/lo split (thread: row r, k-span dq*32) ----
    {
        int k0 = dq*32;
        #pragma unroll
        for (int j = 0; j < 32; j += 2){
            float v0 = eluf(fmaf(x_r, w1_s[k0+j],   b1_s[k0+j]));
            float v1 = eluf(fmaf(x_r, w1_s[k0+j+1], b1_s[k0+j+1]));
            union { __nv_bfloat16 h[2]; uint32_t u; } hi, lo;
            hi.h[0] = __float2bfloat16(v0);
            hi.h[1] = __float2bfloat16(v1);
            lo.h[0] = __float2bfloat16(v0 - __bfloat162float(hi.h[0]));
            lo.h[1] = __float2bfloat16(v1 - __bfloat162float(hi.h[1]));
            *(uint32_t*)(HHI + r*PWB + (k0+j)*2) = hi.u;
            *(uint32_t*)(HLO + r*PWB + (k0+j)*2) = lo.u;
        }
    }

    const uint32_t sb  = smem_u32(sm1);
    const uint32_t aHI = sb + OFF_HHI, aLO = sb + OFF_HLO, wtb = sb + OFF_WT;
    const int tw = wid >> 2, q = wid & 3;
    const uint32_t bHI = wtb + (uint32_t)tw*2*34816;
    const uint32_t bLO = bHI + 34816;
    const uint32_t a_off = (uint32_t)(((lane & 7) + 8*((lane>>3)&1)) * PWB + ((lane>>4)&1)*16);
    const uint32_t b_off = (uint32_t)(((lane & 7) + q*32) * PWB + ((lane>>3)&1)*16);

    float yr[64];
    float s = 0.f, ssq = 0.f;

    #pragma unroll
    for (int c = 0; c < 2; c++){
        // ---- stage weight chunk: 4 tiles of 128x136 bf16 (flat copies) ----
        #pragma unroll
        for (int t2 = 0; t2 < 4; t2++){
            const uint4* src = (const uint4*)(g_wprep
                + ((size_t)((f*2 + (t2>>1))*2 + (t2&1)))*256*PW + (size_t)c*128*PW);
            uint4* dst = (uint4*)(WT + t2*34816);
            for (int u = tid; u < 2176; u += 256) dst[u] = src[u];
        }
        __syncthreads();   // also orders h writes before first ldmatrix

        // ---- MMA: acc[m-tile][n-tile][frag] over 8 ksteps x 3 split terms ----
        float acc[4][4][4];
        #pragma unroll
        for (int i = 0; i < 4; i++)
            #pragma unroll
            for (int j2 = 0; j2 < 4; j2++)
                #pragma unroll
                for (int k2 = 0; k2 < 4; k2++) acc[i][j2][k2] = 0.f;

        #pragma unroll 2
        for (int kk = 0; kk < 8; kk++){
            uint32_t Ah[4][4], Al[4][4], Bh[4][2], Bl[4][2];
            #pragma unroll
            for (int mt = 0; mt < 4; mt++){
                uint32_t aa = (uint32_t)(mt*(16*PWB)) + a_off + kk*32;
                ldsm_x4(Ah[mt], aHI + aa);
                ldsm_x4(Al[mt], aLO + aa);
            }
            #pragma unroll
            for (int nt = 0; nt < 4; nt++){
                uint32_t bb = (uint32_t)(nt*(8*PWB)) + b_off + kk*32;
                ldsm_x2(Bh[nt], bHI + bb);
                ldsm_x2(Bl[nt], bLO + bb);
            }
            #pragma unroll
            for (int mt = 0; mt < 4; mt++)
                #pragma unroll
                for (int nt = 0; nt < 4; nt++){
                    mma16816(acc[mt][nt], Ah[mt], Bh[nt]);   // hi*hi
                    mma16816(acc[mt][nt], Ah[mt], Bl[nt]);   // hi*lo
                    mma16816(acc[mt][nt], Al[mt], Bh[nt]);   // lo*hi
                }
        }
        __syncthreads();   // all warps done reading WT

        // ---- accums -> SMEM overlay (proj at WT, gate at WT+34048) ----
        {
            float* pac = (float*)(WT + tw*34048);
            #pragma unroll
            for (int mt = 0; mt < 4; mt++)
                #pragma unroll
                for (int nt = 0; nt < 4; nt++)
                    #pragma unroll
                    for (int fr = 0; fr < 4; fr++){
                        int m  = mt*16 + (lane>>2) + 8*(fr>>1);
                        int dl = q*32 + nt*8 + (lane&3)*2 + (fr&1);
                        pac[m*PA + dl] = acc[mt][nt][fr];
                    }
        }
        __syncthreads();

        // ---- epilogue: y = skip + sigmoid(gate)*(proj) (pre-LN), into regs ----
        {
            const float* pp = (const float*)WT;
            const float* pg = pp + 8512;
            #pragma unroll 8
            for (int j = 0; j < 32; j++){
                int dl = dq*32 + j, dg = c*128 + dl;
                float p = pp[r*PA + dl] + b2_s[dg];
                float g = sigf(pg[r*PA + dl] + bg_s[dg]);
                float y = fmaf(x_r, ws_s[dg], bs_s[dg]) + g * p;
                yr[c*32 + j] = y;
                s += y; ssq = fmaf(y, y, ssq);
            }
        }
        __syncthreads();   // WT reused next chunk
    }

    // ---- LayerNorm stats (row r = 4 consecutive lanes) ----
    s   += __shfl_xor_sync(0xffffffffu, s, 1);   ssq += __shfl_xor_sync(0xffffffffu, ssq, 1);
    s   += __shfl_xor_sync(0xffffffffu, s, 2);   ssq += __shfl_xor_sync(0xffffffffu, ssq, 2);
    const float mu  = s * (1.f/256.f);
    const float var = ssq * (1.f/256.f) - mu*mu;
    const float rs  = rsqrtf(var + 1e-5f);

    // ---- normalize + write stacked ----
    {
        float* orow = g_stacked + ((size_t)(pbase + r)*NF + f)*Dm;
        #pragma unroll
        for (int c = 0; c < 2; c++)
            #pragma unroll
            for (int j4 = 0; j4 < 32; j4 += 4){
                int dg = c*128 + dq*32 + j4;
                float4 o;
                o.x = fmaf((yr[c*32+j4+0]-mu)*rs, lng_s[dg+0], lnb_s[dg+0]);
                o.y = fmaf((yr[c*32+j4+1]-mu)*rs, lng_s[dg+1], lnb_s[dg+1]);
                o.z = fmaf((yr[c*32+j4+2]-mu)*rs, lng_s[dg+2], lnb_s[dg+2]);
                o.w = fmaf((yr[c*32+j4+3]-mu)*rs, lng_s[dg+3], lnb_s[dg+3]);
                *(float4*)(orow + dg) = o;
            }
    }

    // ---- pooled partials: A[d] = sum_rows rs*y ; B = sum_rows rs*mu ----
    #pragma unroll
    for (int c = 0; c < 2; c++)
        #pragma unroll
        for (int j = 0; j < 32; j++){
            float v = rs * yr[c*32 + j];
            v += __shfl_xor_sync(0xffffffffu, v, 4);
            v += __shfl_xor_sync(0xffffffffu, v, 8);
            v += __shfl_xor_sync(0xffffffffu, v, 16);
            if (lane < 4) poolw[wid*256 + c*128 + lane*32 + j] = v;
        }
    {
        float v = rs * mu;
        v += __shfl_xor_sync(0xffffffffu, v, 1);
        v += __shfl_xor_sync(0xffffffffu, v, 2);
        v += __shfl_xor_sync(0xffffffffu, v, 4);
        v += __shfl_xor_sync(0xffffffffu, v, 8);
        v += __shfl_xor_sync(0xffffffffu, v, 16);
        if (lane == 0) poolb[wid] = v * 0.25f;   // 4 lanes per row over-count
    }
    __syncthreads();
    {
        float sA = 0.f;
        #pragma unroll
        for (int w = 0; w < 8; w++) sA += poolw[w*256 + tid];
        atomicAdd(&g_pooledA[((size_t)b*NF + f)*Dm + tid], sA);
        if (tid == 0){
            float sB = 0.f;
            #pragma unroll
            for (int w = 0; w < 8; w++) sB += poolb[w];
            atomicAdd(&g_pooledB[b*NF + f], sB);
        }
    }
}

// ---------------------------------------------------------------------------
// Pass 2: weight GRN + softmax. grid = B, 256 threads.
// fp[f,d] = lng[f,d]*(pooledA - pooledB[f])/Tt + lnb[f,d]
// ---------------------------------------------------------------------------
__global__ void __launch_bounds__(256,1) vsn_pass2(
    const float* __restrict__ lng,const float* __restrict__ lnb,
    const float* __restrict__ W1, const float* __restrict__ B1,
    const float* __restrict__ W2, const float* __restrict__ B2,
    const float* __restrict__ Wg, const float* __restrict__ Bg,
    const float* __restrict__ Ws, const float* __restrict__ Bs,
    const float* __restrict__ LNg,const float* __restrict__ LNb,
    float* wout)
{
    __shared__ float fp_s[NF*Dm];
    __shared__ float hw_s[Dm];
    __shared__ float part[3][8][NF];
    __shared__ float sb_s[NF];

    const int b = blockIdx.x, tid = threadIdx.x;
    const int k = tid & 31, pt = tid >> 5;
    const float invT = 1.f/(float)Tt;

    if (tid < NF) sb_s[tid] = g_pooledB[b*NF + tid];
    __syncthreads();
    for (int i = tid; i < NF*Dm; i += 256)
        fp_s[i] = fmaf(lng[i]*(g_pooledA[(size_t)b*NF*Dm + i] - sb_s[i >> 8]), invT, lnb[i]);
    __syncthreads();

    {
        float acc = B1[tid];
        const float* wc = W1 + tid;
        #pragma unroll 4
        for (int i = 0; i < NF*Dm; i++)
            acc = fmaf(fp_s[i], wc[(size_t)i*Dm], acc);
        hw_s[tid] = eluf(acc);
    }
    {
        float acc = 0.f;
        const float* wc = Ws + k;
        int i0 = pt * 1024;
        #pragma unroll 4
        for (int i = i0; i < i0 + 1024; i++)
            acc = fmaf(fp_s[i], wc[(size_t)i*NF], acc);
        part[0][pt][k] = acc;
    }
    __syncthreads();
    {
        float a2 = 0.f, a3 = 0.f;
        int d0 = pt * 32;
        #pragma unroll
        for (int d = d0; d < d0 + 32; d++){
            float h = hw_s[d];
            a2 = fmaf(h, W2[d*NF + k], a2);
            a3 = fmaf(h, Wg[d*NF + k], a3);
        }
        part[1][pt][k] = a2; part[2][pt][k] = a3;
    }
    __syncthreads();

    if (tid < 32){
        float sk = Bs[k], pw = B2[k], gw = Bg[k];
        #pragma unroll
        for (int p = 0; p < 8; p++){ sk += part[0][p][k]; pw += part[1][p][k]; gw += part[2][p][k]; }
        float v = sk + sigf(gw) * pw;
        float s = v, ssq = v*v;
        #pragma unroll
        for (int o = 16; o > 0; o >>= 1){
            s   += __shfl_xor_sync(0xffffffffu, s, o);
            ssq += __shfl_xor_sync(0xffffffffu, ssq, o);
        }
        float mu = s * (1.f/32.f);
        float var = ssq * (1.f/32.f) - mu*mu;
        float y = fmaf((v - mu) * rsqrtf(var + 1e-5f), LNg[k], LNb[k]);
        float mx = y;
        #pragma unroll
        for (int o = 16; o > 0; o >>= 1) mx = fmaxf(mx, __shfl_xor_sync(0xffffffffu, mx, o));
        float e = expf(y - mx);
        float se = e;
        #pragma unroll
        for (int o = 16; o > 0; o >>= 1) se += __shfl_xor_sync(0xffffffffu, se, o);
        float w = e / se;
        g_weights[b*NF + k] = w;
        if (wout) wout[b*NF + k] = w;
    }
}

// ---------------------------------------------------------------------------
// Pass 3: selected = einsum(stacked, weights) — DRAM-roofline, unchanged.
// ---------------------------------------------------------------------------
__global__ void __launch_bounds__(256,1) vsn_pass3(float* __restrict__ out)
{
    __shared__ float w_s[NF];
    const int p = blockIdx.x;
    const int b = p >> 9;
    const int tid = threadIdx.x;
    if (tid < NF) w_s[tid] = g_weights[b*NF + tid];
    __syncthreads();
    const float* base = g_stacked + (size_t)p*NF*Dm + tid;
    float acc = 0.f;
    #pragma unroll
    for (int f2 = 0; f2 < NF; f2++)
        acc = fmaf(base[(size_t)f2*Dm], w_s[f2], acc);
    out[(size_t)p*Dm + tid] = acc;
}

// ---------------------------------------------------------------------------
extern "C" void kernel_launch(void* const* d_in, const int* in_sizes, int n_in,
                              void* d_out, int out_size)
{
    const float* x   = (const float*)d_in[0];
    const float* w1  = (const float*)d_in[1];
    const float* b1  = (const float*)d_in[2];
    const float* w2  = (const float*)d_in[3];
    const float* b2  = (const float*)d_in[4];
    const float* wg  = (const float*)d_in[5];
    const float* bg  = (const float*)d_in[6];
    const float* ws  = (const float*)d_in[7];
    const float* bs  = (const float*)d_in[8];
    const float* lng = (const float*)d_in[9];
    const float* lnb = (const float*)d_in[10];
    const float* W1  = (const float*)d_in[11];
    const float* B1  = (const float*)d_in[12];
    const float* W2  = (const float*)d_in[13];
    const float* B2  = (const float*)d_in[14];
    const float* Wg  = (const float*)d_in[15];
    const float* Bg  = (const float*)d_in[16];
    const float* Ws  = (const float*)d_in[17];
    const float* Bs  = (const float*)d_in[18];
    const float* LNg = (const float*)d_in[19];
    const float* LNb = (const float*)d_in[20];

    cudaFuncSetAttribute(vsn_pass1, cudaFuncAttributeMaxDynamicSharedMemorySize, SMEM1_BYTES);

    float* out = (float*)d_out;
    float* wout = (out_size > BT*Dm) ? out + (size_t)BT*Dm : nullptr;

    vsn_prep<<<128, 256>>>(w2, wg);
    vsn_zero<<<(Bb*NF*Dm + 255)/256, 256>>>();
    dim3 g1(NF, BT/MT);
    vsn_pass1<<<g1, 256, SMEM1_BYTES>>>(x, w1, b1, b2, bg, ws, bs, lng, lnb);
    vsn_pass2<<<Bb, 256>>>(lng, lnb, W1, B1, W2, B2, Wg, Bg, Ws, Bs, LNg, LNb, wout);
    vsn_pass3<<<BT, 256>>>(out);
}

// round 5
// speedup vs baseline: 2.0949x; 1.8968x over previous
#include <cuda_runtime.h>
#include <cuda_bf16.h>
#include <math.h>
#include <stdint.h>

#define NF 32
#define Dm 256
#define Hh 128
#define Bb 16
#define Tt 512
#define BT (Bb*Tt)      // 8192 positions
#define MT 64           // positions per CTA in pass1
#define PW 136          // bf16 pitch (elems) of prepped weight / h tiles
#define PWB 272         // bytes
#define PA 133          // fp32 pitch of accum overlay

// ---------------- scratch (device globals; no runtime allocation) ----------
__device__ float g_stacked[(size_t)BT*NF*Dm];   // 268 MB post-LN stacked (B,T,F,D)
__device__ float g_pooledA[Bb*NF*Dm];           // sum_t rs_t * y[t,d]
__device__ float g_pooledB[Bb*NF];              // sum_t rs_t * mu_t
__device__ float g_weights[Bb*NF];
__device__ float g_h1[Bb*Dm];                   // split-K partials of fp@W1
__device__ float g_sk[Bb*NF];                   // split-K partials of fp@Ws
__device__ int   g_cnt;
// prepped weights: [f][tensor][part][d=256][k pitch 136] bf16  (part: 0=hi,1=lo)
__device__ __nv_bfloat16 g_wprep[128 * 256 * PW];   // 8.9 MB

// ---------------- helpers --------------------------------------------------
__device__ __forceinline__ uint32_t smem_u32(const void* p){
    uint32_t a;
    asm("{ .reg .u64 t; cvta.to.shared.u64 t, %1; cvt.u32.u64 %0, t; }" : "=r"(a) : "l"(p));
    return a;
}
__device__ __forceinline__ void ldsm_x4(uint32_t (&r)[4], uint32_t a){
    asm volatile("ldmatrix.sync.aligned.m8n8.x4.shared.b16 {%0,%1,%2,%3}, [%4];"
        : "=r"(r[0]),"=r"(r[1]),"=r"(r[2]),"=r"(r[3]) : "r"(a));
}
__device__ __forceinline__ void ldsm_x2(uint32_t (&r)[2], uint32_t a){
    asm volatile("ldmatrix.sync.aligned.m8n8.x2.shared.b16 {%0,%1}, [%2];"
        : "=r"(r[0]),"=r"(r[1]) : "r"(a));
}
__device__ __forceinline__ void mma16816(float (&c)[4], const uint32_t (&a)[4], const uint32_t (&b)[2]){
    asm volatile("mma.sync.aligned.m16n8k16.row.col.f32.bf16.bf16.f32 "
        "{%0,%1,%2,%3}, {%4,%5,%6,%7}, {%8,%9}, {%0,%1,%2,%3};"
        : "+f"(c[0]),"+f"(c[1]),"+f"(c[2]),"+f"(c[3])
        : "r"(a[0]),"r"(a[1]),"r"(a[2]),"r"(a[3]), "r"(b[0]),"r"(b[1]));
}
__device__ __forceinline__ float eluf(float z){ return z > 0.f ? z : expm1f(z); }
__device__ __forceinline__ float sigf(float z){ return __fdividef(1.f, 1.f + __expf(-z)); }

// ---------------------------------------------------------------------------
// K1: prep (w2/wg -> bf16 hi/lo transposed pitch-136 images) + zero scratch.
// grid = 130: blocks 0..127 prep, 128..129 zero.
// ---------------------------------------------------------------------------
__global__ void __launch_bounds__(256,1) vsn_prep(const float* __restrict__ w2,
                                                  const float* __restrict__ wg)
{
    __shared__ float ts[128][65];
    const int bid = blockIdx.x;
    const int tid = threadIdx.x;

    if (bid >= 128){
        int z = bid - 128;   // 0 or 1
        for (int i = z*65536 + tid; i < z*65536 + 65536; i += 256) g_pooledA[i] = 0.f;
        if (z == 0){
            for (int i = tid; i < Bb*Dm; i += 256) g_h1[i] = 0.f;
            for (int i = tid; i < Bb*NF; i += 256){ g_sk[i] = 0.f; g_pooledB[i] = 0.f; }
            if (tid == 0) g_cnt = 0;
        }
        return;
    }

    const int f = bid >> 2, t = (bid >> 1) & 1, p = bid & 1;
    const float* W = (t ? wg : w2) + (size_t)f*Hh*Dm;       // [k][d]
    __nv_bfloat16* dst = g_wprep + (size_t)bid * 256 * PW;  // [d][k pitch 136]

    for (int dc = 0; dc < 4; dc++){
        #pragma unroll
        for (int i = 0; i < 32; i++){
            int e = tid + i*256;
            int d = e & 63, k = e >> 6;
            ts[k][d] = W[(size_t)k*Dm + dc*64 + d];
        }
        __syncthreads();
        #pragma unroll
        for (int i = 0; i < 4; i++){
            int g = tid + i*256;
            int d = g >> 4, kg = g & 15;
            union { __nv_bfloat16 h[8]; uint4 v; } o;
            #pragma unroll
            for (int j = 0; j < 8; j++){
                float v = ts[kg*8 + j][d];
                __nv_bfloat16 hi = __float2bfloat16(v);
                o.h[j] = p ? __float2bfloat16(v - __bfloat162float(hi)) : hi;
            }
            *(uint4*)(dst + (size_t)(dc*64 + d)*PW + kg*8) = o.v;
        }
        __syncthreads();
    }
}

// ---------------------------------------------------------------------------
// K2 / Pass 1 (mma.sync bf16, 3-term split): per-feature GRN + LN + stacked +
// pooled. grid = (NF, BT/MT) = (32,128), 256 threads, ~185 KB dyn smem.
// ---------------------------------------------------------------------------
#define OFF_HHI 0
#define OFF_HLO 17408
#define OFF_WT  34816
#define OFF_PAR 174080
#define SMEM1_BYTES (174080 + 15392)

extern __shared__ char sm1[];

__global__ void __launch_bounds__(256,1) vsn_pass1(
    const float* __restrict__ x,  const float* __restrict__ w1, const float* __restrict__ b1,
    const float* __restrict__ b2, const float* __restrict__ bg,
    const float* __restrict__ ws, const float* __restrict__ bs,
    const float* __restrict__ lng,const float* __restrict__ lnb)
{
    const int f     = blockIdx.x;
    const int pbase = blockIdx.y * MT;
    const int b     = pbase / Tt;
    const int tid   = threadIdx.x;
    const int lane  = tid & 31;
    const int wid   = tid >> 5;
    const int r     = tid >> 2;       // row 0..63
    const int dq    = tid & 3;        // d-quarter within chunk

    char* HHI = sm1 + OFF_HHI;
    char* HLO = sm1 + OFF_HLO;
    char* WT  = sm1 + OFF_WT;
    float* b2_s = (float*)(sm1 + OFF_PAR);
    float* bg_s = b2_s + 256;
    float* ws_s = bg_s + 256;
    float* bs_s = ws_s + 256;
    float* lng_s= bs_s + 256;
    float* lnb_s= lng_s + 256;
    float* w1_s = lnb_s + 256;
    float* b1_s = w1_s + 128;
    float* poolw= b1_s + 128;        // [8][256]
    float* poolb= poolw + 2048;      // [8]

    b2_s[tid] = b2[f*Dm + tid];
    bg_s[tid] = bg[f*Dm + tid];
    ws_s[tid] = ws[f*Dm + tid];
    bs_s[tid] = bs[f*Dm + tid];
    lng_s[tid]= lng[f*Dm + tid];
    lnb_s[tid]= lnb[f*Dm + tid];
    if (tid < 128){ w1_s[tid] = w1[f*Hh + tid]; b1_s[tid] = b1[f*Hh + tid]; }
    const float x_r = x[(size_t)(pbase + r)*NF + f];
    __syncthreads();

    // h split into bf16 hi/lo rows
    {
        int k0 = dq*32;
        #pragma unroll
        for (int j = 0; j < 32; j += 2){
            float v0 = eluf(fmaf(x_r, w1_s[k0+j],   b1_s[k0+j]));
            float v1 = eluf(fmaf(x_r, w1_s[k0+j+1], b1_s[k0+j+1]));
            union { __nv_bfloat16 h[2]; uint32_t u; } hi, lo;
            hi.h[0] = __float2bfloat16(v0);
            hi.h[1] = __float2bfloat16(v1);
            lo.h[0] = __float2bfloat16(v0 - __bfloat162float(hi.h[0]));
            lo.h[1] = __float2bfloat16(v1 - __bfloat162float(hi.h[1]));
            *(uint32_t*)(HHI + r*PWB + (k0+j)*2) = hi.u;
            *(uint32_t*)(HLO + r*PWB + (k0+j)*2) = lo.u;
        }
    }

    const uint32_t sb  = smem_u32(sm1);
    const uint32_t aHI = sb + OFF_HHI, aLO = sb + OFF_HLO, wtb = sb + OFF_WT;
    const int tw = wid >> 2, q = wid & 3;
    const uint32_t bHI = wtb + (uint32_t)tw*2*34816;
    const uint32_t bLO = bHI + 34816;
    const uint32_t a_off = (uint32_t)(((lane & 7) + 8*((lane>>3)&1)) * PWB + ((lane>>4)&1)*16);
    const uint32_t b_off = (uint32_t)(((lane & 7) + q*32) * PWB + ((lane>>3)&1)*16);

    float yr[64];
    float s = 0.f, ssq = 0.f;

    #pragma unroll
    for (int c = 0; c < 2; c++){
        #pragma unroll
        for (int t2 = 0; t2 < 4; t2++){
            const uint4* src = (const uint4*)(g_wprep
                + ((size_t)((f*2 + (t2>>1))*2 + (t2&1)))*256*PW + (size_t)c*128*PW);
            uint4* dst = (uint4*)(WT + t2*34816);
            for (int u = tid; u < 2176; u += 256) dst[u] = src[u];
        }
        __syncthreads();

        float acc[4][4][4];
        #pragma unroll
        for (int i = 0; i < 4; i++)
            #pragma unroll
            for (int j2 = 0; j2 < 4; j2++)
                #pragma unroll
                for (int k2 = 0; k2 < 4; k2++) acc[i][j2][k2] = 0.f;

        #pragma unroll 2
        for (int kk = 0; kk < 8; kk++){
            uint32_t Ah[4][4], Al[4][4], Bh[4][2], Bl[4][2];
            #pragma unroll
            for (int mt = 0; mt < 4; mt++){
                uint32_t aa = (uint32_t)(mt*(16*PWB)) + a_off + kk*32;
                ldsm_x4(Ah[mt], aHI + aa);
                ldsm_x4(Al[mt], aLO + aa);
            }
            #pragma unroll
            for (int nt = 0; nt < 4; nt++){
                uint32_t bb = (uint32_t)(nt*(8*PWB)) + b_off + kk*32;
                ldsm_x2(Bh[nt], bHI + bb);
                ldsm_x2(Bl[nt], bLO + bb);
            }
            #pragma unroll
            for (int mt = 0; mt < 4; mt++)
                #pragma unroll
                for (int nt = 0; nt < 4; nt++){
                    mma16816(acc[mt][nt], Ah[mt], Bh[nt]);
                    mma16816(acc[mt][nt], Ah[mt], Bl[nt]);
                    mma16816(acc[mt][nt], Al[mt], Bh[nt]);
                }
        }
        __syncthreads();

        {
            float* pac = (float*)(WT + tw*34048);
            #pragma unroll
            for (int mt = 0; mt < 4; mt++)
                #pragma unroll
                for (int nt = 0; nt < 4; nt++)
                    #pragma unroll
                    for (int fr = 0; fr < 4; fr++){
                        int m  = mt*16 + (lane>>2) + 8*(fr>>1);
                        int dl = q*32 + nt*8 + (lane&3)*2 + (fr&1);
                        pac[m*PA + dl] = acc[mt][nt][fr];
                    }
        }
        __syncthreads();

        {
            const float* pp = (const float*)WT;
            const float* pg = pp + 8512;
            #pragma unroll 8
            for (int j = 0; j < 32; j++){
                int dl = dq*32 + j, dg = c*128 + dl;
                float p = pp[r*PA + dl] + b2_s[dg];
                float g = sigf(pg[r*PA + dl] + bg_s[dg]);
                float y = fmaf(x_r, ws_s[dg], bs_s[dg]) + g * p;
                yr[c*32 + j] = y;
                s += y; ssq = fmaf(y, y, ssq);
            }
        }
        __syncthreads();
    }

    s   += __shfl_xor_sync(0xffffffffu, s, 1);   ssq += __shfl_xor_sync(0xffffffffu, ssq, 1);
    s   += __shfl_xor_sync(0xffffffffu, s, 2);   ssq += __shfl_xor_sync(0xffffffffu, ssq, 2);
    const float mu  = s * (1.f/256.f);
    const float var = ssq * (1.f/256.f) - mu*mu;
    const float rs  = rsqrtf(var + 1e-5f);

    {
        float* orow = g_stacked + ((size_t)(pbase + r)*NF + f)*Dm;
        #pragma unroll
        for (int c = 0; c < 2; c++)
            #pragma unroll
            for (int j4 = 0; j4 < 32; j4 += 4){
                int dg = c*128 + dq*32 + j4;
                float4 o;
                o.x = fmaf((yr[c*32+j4+0]-mu)*rs, lng_s[dg+0], lnb_s[dg+0]);
                o.y = fmaf((yr[c*32+j4+1]-mu)*rs, lng_s[dg+1], lnb_s[dg+1]);
                o.z = fmaf((yr[c*32+j4+2]-mu)*rs, lng_s[dg+2], lnb_s[dg+2]);
                o.w = fmaf((yr[c*32+j4+3]-mu)*rs, lng_s[dg+3], lnb_s[dg+3]);
                *(float4*)(orow + dg) = o;
            }
    }

    #pragma unroll
    for (int c = 0; c < 2; c++)
        #pragma unroll
        for (int j = 0; j < 32; j++){
            float v = rs * yr[c*32 + j];
            v += __shfl_xor_sync(0xffffffffu, v, 4);
            v += __shfl_xor_sync(0xffffffffu, v, 8);
            v += __shfl_xor_sync(0xffffffffu, v, 16);
            if (lane < 4) poolw[wid*256 + c*128 + lane*32 + j] = v;
        }
    {
        float v = rs * mu;
        v += __shfl_xor_sync(0xffffffffu, v, 1);
        v += __shfl_xor_sync(0xffffffffu, v, 2);
        v += __shfl_xor_sync(0xffffffffu, v, 4);
        v += __shfl_xor_sync(0xffffffffu, v, 8);
        v += __shfl_xor_sync(0xffffffffu, v, 16);
        if (lane == 0) poolb[wid] = v * 0.25f;
    }
    __syncthreads();
    {
        float sA = 0.f;
        #pragma unroll
        for (int w = 0; w < 8; w++) sA += poolw[w*256 + tid];
        atomicAdd(&g_pooledA[((size_t)b*NF + f)*Dm + tid], sA);
        if (tid == 0){
            float sB = 0.f;
            #pragma unroll
            for (int w = 0; w < 8; w++) sB += poolb[w];
            atomicAdd(&g_pooledB[b*NF + f], sB);
        }
    }
}

// ---------------------------------------------------------------------------
// K3 / Pass 2: weight GRN + softmax, split-K over features.
// grid = 32 (one CTA per feature f = 256 rows of W1/Ws), 256 threads.
// Last CTA (counter) finalizes: elu, W2/Wg GEMVs, LN, softmax.
// ---------------------------------------------------------------------------
__global__ void __launch_bounds__(256,1) vsn_pass2(
    const float* __restrict__ lng,const float* __restrict__ lnb,
    const float* __restrict__ W1, const float* __restrict__ B1,
    const float* __restrict__ W2, const float* __restrict__ B2,
    const float* __restrict__ Wg, const float* __restrict__ Bg,
    const float* __restrict__ Ws, const float* __restrict__ Bs,
    const float* __restrict__ LNg,const float* __restrict__ LNb,
    float* wout)
{
    __shared__ float fp_s[256][16];   // [j][b]
    __shared__ float pb_s[16];
    __shared__ float hw_s[Dm];
    __shared__ float part2[8][NF], part3[8][NF];
    __shared__ int s_last;

    const int f = blockIdx.x, tid = threadIdx.x;
    const float invT = 1.f/(float)Tt;

    if (tid < 16) pb_s[tid] = g_pooledB[tid*NF + f];
    __syncthreads();

    // fp[j][b] for this feature's 256 rows
    {
        const float lg = lng[f*Dm + tid], lb = lnb[f*Dm + tid];
        #pragma unroll
        for (int b = 0; b < 16; b++){
            float pa = g_pooledA[((size_t)b*NF + f)*Dm + tid];
            fp_s[tid][b] = fmaf(lg*(pa - pb_s[b]), invT, lb);
        }
    }
    __syncthreads();

    // split-K: this CTA's contribution to hw_pre[b][d] (d = tid)
    {
        float acc[16];
        #pragma unroll
        for (int b = 0; b < 16; b++) acc[b] = 0.f;
        const float* w1p = W1 + (size_t)f*256*Dm + tid;
        #pragma unroll 4
        for (int j = 0; j < 256; j++){
            float w = w1p[(size_t)j*Dm];
            const float4* fv = (const float4*)fp_s[j];
            float4 f0 = fv[0], f1 = fv[1], f2 = fv[2], f3 = fv[3];
            acc[0]  = fmaf(f0.x, w, acc[0]);  acc[1]  = fmaf(f0.y, w, acc[1]);
            acc[2]  = fmaf(f0.z, w, acc[2]);  acc[3]  = fmaf(f0.w, w, acc[3]);
            acc[4]  = fmaf(f1.x, w, acc[4]);  acc[5]  = fmaf(f1.y, w, acc[5]);
            acc[6]  = fmaf(f1.z, w, acc[6]);  acc[7]  = fmaf(f1.w, w, acc[7]);
            acc[8]  = fmaf(f2.x, w, acc[8]);  acc[9]  = fmaf(f2.y, w, acc[9]);
            acc[10] = fmaf(f2.z, w, acc[10]); acc[11] = fmaf(f2.w, w, acc[11]);
            acc[12] = fmaf(f3.x, w, acc[12]); acc[13] = fmaf(f3.y, w, acc[13]);
            acc[14] = fmaf(f3.z, w, acc[14]); acc[15] = fmaf(f3.w, w, acc[15]);
        }
        #pragma unroll
        for (int b = 0; b < 16; b++)
            atomicAdd(&g_h1[b*Dm + tid], acc[b]);
    }

    // split-K skip: sk[b][k], thread handles (k, b) and (k, b+8)
    {
        const int k = tid & 31, bg2 = tid >> 5;
        float a0 = 0.f, a1 = 0.f;
        const float* wsp = Ws + (size_t)f*256*NF + k;
        #pragma unroll 4
        for (int j = 0; j < 256; j++){
            float w = wsp[(size_t)j*NF];
            a0 = fmaf(fp_s[j][bg2],   w, a0);
            a1 = fmaf(fp_s[j][bg2+8], w, a1);
        }
        atomicAdd(&g_sk[bg2*NF + k], a0);
        atomicAdd(&g_sk[(bg2+8)*NF + k], a1);
    }

    // arrival + last-block finalize
    __threadfence();
    __syncthreads();
    if (tid == 0) s_last = (atomicAdd(&g_cnt, 1) == 31) ? 1 : 0;
    __syncthreads();
    if (!s_last) return;
    __threadfence();

    for (int b = 0; b < 16; b++){
        hw_s[tid] = eluf(__ldcg(&g_h1[b*Dm + tid]) + B1[tid]);
        __syncthreads();
        {
            const int k = tid & 31, pt = tid >> 5;
            float a2 = 0.f, a3 = 0.f;
            const int d0 = pt*32;
            #pragma unroll
            for (int d = d0; d < d0 + 32; d++){
                float h = hw_s[d];
                a2 = fmaf(h, W2[d*NF + k], a2);
                a3 = fmaf(h, Wg[d*NF + k], a3);
            }
            part2[pt][k] = a2; part3[pt][k] = a3;
        }
        __syncthreads();
        if (tid < 32){
            const int k = tid;
            float pw = B2[k], gw = Bg[k];
            #pragma unroll
            for (int p = 0; p < 8; p++){ pw += part2[p][k]; gw += part3[p][k]; }
            float sk = __ldcg(&g_sk[b*NF + k]) + Bs[k];
            float v = sk + sigf(gw) * pw;
            float s = v, ssq = v*v;
            #pragma unroll
            for (int o = 16; o > 0; o >>= 1){
                s   += __shfl_xor_sync(0xffffffffu, s, o);
                ssq += __shfl_xor_sync(0xffffffffu, ssq, o);
            }
            float mu = s * (1.f/32.f);
            float var = ssq * (1.f/32.f) - mu*mu;
            float y = fmaf((v - mu) * rsqrtf(var + 1e-5f), LNg[k], LNb[k]);
            float mx = y;
            #pragma unroll
            for (int o = 16; o > 0; o >>= 1) mx = fmaxf(mx, __shfl_xor_sync(0xffffffffu, mx, o));
            float e = expf(y - mx);
            float se = e;
            #pragma unroll
            for (int o = 16; o > 0; o >>= 1) se += __shfl_xor_sync(0xffffffffu, se, o);
            float w = e / se;
            g_weights[b*NF + k] = w;
            if (wout) wout[b*NF + k] = w;
        }
        __syncthreads();
    }
}

// ---------------------------------------------------------------------------
// K4 / Pass 3: selected = einsum(stacked, weights) — DRAM-roofline.
// ---------------------------------------------------------------------------
__global__ void __launch_bounds__(256,1) vsn_pass3(float* __restrict__ out)
{
    __shared__ float w_s[NF];
    const int p = blockIdx.x;
    const int b = p >> 9;
    const int tid = threadIdx.x;
    if (tid < NF) w_s[tid] = g_weights[b*NF + tid];
    __syncthreads();
    const float* base = g_stacked + (size_t)p*NF*Dm + tid;
    float acc = 0.f;
    #pragma unroll
    for (int f2 = 0; f2 < NF; f2++)
        acc = fmaf(base[(size_t)f2*Dm], w_s[f2], acc);
    out[(size_t)p*Dm + tid] = acc;
}

// ---------------------------------------------------------------------------
extern "C" void kernel_launch(void* const* d_in, const int* in_sizes, int n_in,
                              void* d_out, int out_size)
{
    const float* x   = (const float*)d_in[0];
    const float* w1  = (const float*)d_in[1];
    const float* b1  = (const float*)d_in[2];
    const float* w2  = (const float*)d_in[3];
    const float* b2  = (const float*)d_in[4];
    const float* wg  = (const float*)d_in[5];
    const float* bg  = (const float*)d_in[6];
    const float* ws  = (const float*)d_in[7];
    const float* bs  = (const float*)d_in[8];
    const float* lng = (const float*)d_in[9];
    const float* lnb = (const float*)d_in[10];
    const float* W1  = (const float*)d_in[11];
    const float* B1  = (const float*)d_in[12];
    const float* W2  = (const float*)d_in[13];
    const float* B2  = (const float*)d_in[14];
    const float* Wg  = (const float*)d_in[15];
    const float* Bg  = (const float*)d_in[16];
    const float* Ws  = (const float*)d_in[17];
    const float* Bs  = (const float*)d_in[18];
    const float* LNg = (const float*)d_in[19];
    const float* LNb = (const float*)d_in[20];

    cudaFuncSetAttribute(vsn_pass1, cudaFuncAttributeMaxDynamicSharedMemorySize, SMEM1_BYTES);

    float* out = (float*)d_out;
    float* wout = (out_size > BT*Dm) ? out + (size_t)BT*Dm : nullptr;

    vsn_prep<<<130, 256>>>(w2, wg);
    dim3 g1(NF, BT/MT);
    vsn_pass1<<<g1, 256, SMEM1_BYTES>>>(x, w1, b1, b2, bg, ws, bs, lng, lnb);
    vsn_pass2<<<32, 256>>>(lng, lnb, W1, B1, W2, B2, Wg, Bg, Ws, Bs, LNg, LNb, wout);
    vsn_pass3<<<BT, 256>>>(out);
}

// round 6
// speedup vs baseline: 2.8244x; 1.3482x over previous
#include <cuda_runtime.h>
#include <cuda_bf16.h>
#include <math.h>
#include <stdint.h>

#define NF 32
#define Dm 256
#define Hh 128
#define Bb 16
#define Tt 512
#define BT (Bb*Tt)      // 8192 positions
#define MT 64           // positions per CTA in pass1
#define PW 136          // bf16 pitch (elems) of prepped weight / h tiles
#define PWB 272         // bytes

// ---------------- scratch (device globals; no runtime allocation) ----------
__device__ float g_stacked[(size_t)BT*NF*Dm];   // 268 MB (B,T,F,D)
__device__ float g_pooledA[Bb*NF*Dm];           // sum_t rs_t * y[t,d]
__device__ float g_pooledB[Bb*NF];              // sum_t rs_t * mu_t
__device__ float g_weights[Bb*NF];
__device__ float g_h1[Bb*Dm];                   // split-K partials of fp@W1
__device__ float g_sk[Bb*NF];                   // split-K partials of fp@Ws
__device__ int   g_cnt;
// prepped weights: [f][tensor][part][d=256][k pitch 136] bf16 (part: 0=hi,1=lo)
__device__ __nv_bfloat16 g_wprep[128 * 256 * PW];   // 8.9 MB

// ---------------- helpers --------------------------------------------------
__device__ __forceinline__ uint32_t smem_u32(const void* p){
    uint32_t a;
    asm("{ .reg .u64 t; cvta.to.shared.u64 t, %1; cvt.u32.u64 %0, t; }" : "=r"(a) : "l"(p));
    return a;
}
__device__ __forceinline__ void ldsm_x4(uint32_t (&r)[4], uint32_t a){
    asm volatile("ldmatrix.sync.aligned.m8n8.x4.shared.b16 {%0,%1,%2,%3}, [%4];"
        : "=r"(r[0]),"=r"(r[1]),"=r"(r[2]),"=r"(r[3]) : "r"(a));
}
__device__ __forceinline__ void ldsm_x2(uint32_t (&r)[2], uint32_t a){
    asm volatile("ldmatrix.sync.aligned.m8n8.x2.shared.b16 {%0,%1}, [%2];"
        : "=r"(r[0]),"=r"(r[1]) : "r"(a));
}
__device__ __forceinline__ void mma16816(float* c, const uint32_t (&a)[4], const uint32_t (&b)[2]){
    asm volatile("mma.sync.aligned.m16n8k16.row.col.f32.bf16.bf16.f32 "
        "{%0,%1,%2,%3}, {%4,%5,%6,%7}, {%8,%9}, {%0,%1,%2,%3};"
        : "+f"(c[0]),"+f"(c[1]),"+f"(c[2]),"+f"(c[3])
        : "r"(a[0]),"r"(a[1]),"r"(a[2]),"r"(a[3]), "r"(b[0]),"r"(b[1]));
}
__device__ __forceinline__ float eluf(float z){ return z > 0.f ? z : expm1f(z); }
__device__ __forceinline__ float sigf(float z){ return __fdividef(1.f, 1.f + __expf(-z)); }

// ---------------------------------------------------------------------------
// K1: prep (w2/wg -> bf16 hi/lo transposed pitch-136 images) + zero scratch.
// grid = 130: blocks 0..127 prep, 128..129 zero.
// ---------------------------------------------------------------------------
__global__ void __launch_bounds__(256,1) vsn_prep(const float* __restrict__ w2,
                                                  const float* __restrict__ wg)
{
    __shared__ float ts[128][65];
    const int bid = blockIdx.x;
    const int tid = threadIdx.x;

    if (bid >= 128){
        int z = bid - 128;
        for (int i = z*65536 + tid; i < z*65536 + 65536; i += 256) g_pooledA[i] = 0.f;
        if (z == 0){
            for (int i = tid; i < Bb*Dm; i += 256) g_h1[i] = 0.f;
            for (int i = tid; i < Bb*NF; i += 256){ g_sk[i] = 0.f; g_pooledB[i] = 0.f; }
            if (tid == 0) g_cnt = 0;
        }
        return;
    }

    const int f = bid >> 2, t = (bid >> 1) & 1, p = bid & 1;
    const float* W = (t ? wg : w2) + (size_t)f*Hh*Dm;       // [k][d]
    __nv_bfloat16* dst = g_wprep + (size_t)bid * 256 * PW;  // [d][k pitch 136]

    for (int dc = 0; dc < 4; dc++){
        #pragma unroll
        for (int i = 0; i < 32; i++){
            int e = tid + i*256;
            int d = e & 63, k = e >> 6;
            ts[k][d] = W[(size_t)k*Dm + dc*64 + d];
        }
        __syncthreads();
        #pragma unroll
        for (int i = 0; i < 4; i++){
            int g = tid + i*256;
            int d = g >> 4, kg = g & 15;
            union { __nv_bfloat16 h[8]; uint4 v; } o;
            #pragma unroll
            for (int j = 0; j < 8; j++){
                float v = ts[kg*8 + j][d];
                __nv_bfloat16 hi = __float2bfloat16(v);
                o.h[j] = p ? __float2bfloat16(v - __bfloat162float(hi)) : hi;
            }
            *(uint4*)(dst + (size_t)(dc*64 + d)*PW + kg*8) = o.v;
        }
        __syncthreads();
    }
}

// ---------------------------------------------------------------------------
// K2 / Pass 1: HMMA bf16 3-term split, 2 CTAs/SM, in-register epilogue,
// pre-LN y -> gmem, L2-hot normalize readback.
// grid = (NF, BT/MT) = (32,128), 256 threads, 111872 B dyn smem.
// ---------------------------------------------------------------------------
#define OFF_HHI 0
#define OFF_HLO 17408
#define OFF_WT  34816           // 4 x 17408 = 69632 (w2hi,w2lo,wghi,wglo)
#define OFF_B2  104448
#define OFF_BG  105472
#define OFF_WS  106496
#define OFF_BS  107520
#define OFF_LNG 108544
#define OFF_LNB 109568
#define OFF_W1  110592
#define OFF_B1  111104
#define OFF_X   111616
#define SMEM1_BYTES 111872
// overlays inside WT (used only after last MMA):
//  sred   = WT+0     [8][64] f32
//  ssqred = WT+2048  [8][64] f32
//  rs_s   = WT+4096  [64] f32
//  mu_s   = WT+4352  [64] f32
//  pool   = WT+4608  [8][256] f32
//  poolb  = WT+12800 [8] f32

extern __shared__ char sm1[];

__global__ void __launch_bounds__(256,2) vsn_pass1(
    const float* __restrict__ x,  const float* __restrict__ w1, const float* __restrict__ b1,
    const float* __restrict__ b2, const float* __restrict__ bg,
    const float* __restrict__ ws, const float* __restrict__ bs,
    const float* __restrict__ lng,const float* __restrict__ lnb)
{
    const int f     = blockIdx.x;
    const int pbase = blockIdx.y * MT;
    const int b     = pbase / Tt;
    const int tid   = threadIdx.x;
    const int lane  = tid & 31;
    const int wid   = tid >> 5;

    char* HHI = sm1 + OFF_HHI;
    char* HLO = sm1 + OFF_HLO;
    float* b2_s = (float*)(sm1 + OFF_B2);
    float* bg_s = (float*)(sm1 + OFF_BG);
    float* ws_s = (float*)(sm1 + OFF_WS);
    float* bs_s = (float*)(sm1 + OFF_BS);
    float* lng_s= (float*)(sm1 + OFF_LNG);
    float* lnb_s= (float*)(sm1 + OFF_LNB);
    float* w1_s = (float*)(sm1 + OFF_W1);
    float* b1_s = (float*)(sm1 + OFF_B1);
    float* x_s  = (float*)(sm1 + OFF_X);

    // ---- stage params ----
    b2_s[tid] = b2[f*Dm + tid];
    bg_s[tid] = bg[f*Dm + tid];
    ws_s[tid] = ws[f*Dm + tid];
    bs_s[tid] = bs[f*Dm + tid];
    lng_s[tid]= lng[f*Dm + tid];
    lnb_s[tid]= lnb[f*Dm + tid];
    if (tid < 128){ w1_s[tid] = w1[f*Hh + tid]; b1_s[tid] = b1[f*Hh + tid]; }
    if (tid < 64)  x_s[tid] = x[(size_t)(pbase + tid)*NF + f];
    __syncthreads();

    // ---- h split into bf16 hi/lo rows (row r = tid>>2, k-span (tid&3)*32) ----
    {
        const int r = tid >> 2, k0 = (tid & 3)*32;
        const float x_r = x_s[r];
        #pragma unroll
        for (int j = 0; j < 32; j += 2){
            float v0 = eluf(fmaf(x_r, w1_s[k0+j],   b1_s[k0+j]));
            float v1 = eluf(fmaf(x_r, w1_s[k0+j+1], b1_s[k0+j+1]));
            union { __nv_bfloat16 h[2]; uint32_t u; } hi, lo;
            hi.h[0] = __float2bfloat16(v0);
            hi.h[1] = __float2bfloat16(v1);
            lo.h[0] = __float2bfloat16(v0 - __bfloat162float(hi.h[0]));
            lo.h[1] = __float2bfloat16(v1 - __bfloat162float(hi.h[1]));
            *(uint32_t*)(HHI + r*PWB + (k0+j)*2) = hi.u;
            *(uint32_t*)(HLO + r*PWB + (k0+j)*2) = lo.u;
        }
    }

    const uint32_t sb  = smem_u32(sm1);
    const uint32_t aHI = sb + OFF_HHI, aLO = sb + OFF_HLO, wtb = sb + OFF_WT;
    const uint32_t a_off = (uint32_t)(((lane & 7) + 8*((lane>>3)&1)) * PWB + ((lane>>4)&1)*16);
    const uint32_t b_off = (uint32_t)((wid*8 + (lane & 7)) * PWB + ((lane>>3)&1)*16);

    float srow[8], ssqrow[8];
    #pragma unroll
    for (int i = 0; i < 8; i++){ srow[i] = 0.f; ssqrow[i] = 0.f; }

    for (int c = 0; c < 4; c++){
        // ---- stage weight chunk: 4 parts x [64 d-rows][136 k] bf16 ----
        #pragma unroll
        for (int p4 = 0; p4 < 4; p4++){
            const uint4* src = ((const uint4*)g_wprep)
                + (size_t)((f*2 + (p4>>1))*2 + (p4&1))*4352 + (size_t)c*1088;
            uint4* dst = (uint4*)(sm1 + OFF_WT + p4*17408);
            #pragma unroll
            for (int u = tid; u < 1088; u += 256) dst[u] = src[u];
        }
        __syncthreads();   // staging done (also orders h writes before ldsm on c=0)

        float accp[16], accg[16];
        #pragma unroll
        for (int i = 0; i < 16; i++){ accp[i] = 0.f; accg[i] = 0.f; }

        #pragma unroll 2
        for (int kk = 0; kk < 8; kk++){
            uint32_t Bph[2], Bpl[2], Bgh[2], Bgl[2];
            const uint32_t bb = b_off + kk*32;
            ldsm_x2(Bph, wtb + 0*17408 + bb);
            ldsm_x2(Bpl, wtb + 1*17408 + bb);
            ldsm_x2(Bgh, wtb + 2*17408 + bb);
            ldsm_x2(Bgl, wtb + 3*17408 + bb);
            #pragma unroll
            for (int mt = 0; mt < 4; mt++){
                uint32_t Ah[4], Al[4];
                const uint32_t aa = (uint32_t)(mt*(16*PWB)) + a_off + kk*32;
                ldsm_x4(Ah, aHI + aa);
                ldsm_x4(Al, aLO + aa);
                mma16816(accp + mt*4, Ah, Bph);
                mma16816(accp + mt*4, Ah, Bpl);
                mma16816(accp + mt*4, Al, Bph);
                mma16816(accg + mt*4, Ah, Bgh);
                mma16816(accg + mt*4, Ah, Bgl);
                mma16816(accg + mt*4, Al, Bgh);
            }
        }
        __syncthreads();   // all warps done reading WT before next staging

        // ---- in-register epilogue: y pre-LN -> gmem (32B sectors), stats ----
        {
            const int dg0 = c*64 + wid*8 + (lane & 3)*2;
            #pragma unroll
            for (int mt = 0; mt < 4; mt++)
                #pragma unroll
                for (int hf = 0; hf < 2; hf++){
                    const int m = mt*16 + (lane>>2) + 8*hf;
                    const float xm = x_s[m];
                    float p0 = accp[mt*4 + hf*2 + 0] + b2_s[dg0];
                    float p1 = accp[mt*4 + hf*2 + 1] + b2_s[dg0+1];
                    float g0 = sigf(accg[mt*4 + hf*2 + 0] + bg_s[dg0]);
                    float g1 = sigf(accg[mt*4 + hf*2 + 1] + bg_s[dg0+1]);
                    float y0 = fmaf(xm, ws_s[dg0],   bs_s[dg0])   + g0*p0;
                    float y1 = fmaf(xm, ws_s[dg0+1], bs_s[dg0+1]) + g1*p1;
                    float2 yy; yy.x = y0; yy.y = y1;
                    *(float2*)(g_stacked + ((size_t)(pbase + m)*NF + f)*Dm + dg0) = yy;
                    srow[mt*2 + hf] += y0 + y1;
                    ssqrow[mt*2 + hf] = fmaf(y0, y0, fmaf(y1, y1, ssqrow[mt*2 + hf]));
                }
        }
    }

    // ---- LN stats: reduce to per-row mu/rs (WT overlay now free) ----
    __syncthreads();
    float* sred   = (float*)(sm1 + OFF_WT);
    float* ssqred = sred + 512;
    #pragma unroll
    for (int i = 0; i < 8; i++){
        float v = srow[i], q = ssqrow[i];
        v += __shfl_xor_sync(0xffffffffu, v, 1);  q += __shfl_xor_sync(0xffffffffu, q, 1);
        v += __shfl_xor_sync(0xffffffffu, v, 2);  q += __shfl_xor_sync(0xffffffffu, q, 2);
        if ((lane & 3) == 0){
            const int m = (i>>1)*16 + (lane>>2) + 8*(i & 1);
            sred[wid*64 + m]   = v;
            ssqred[wid*64 + m] = q;
        }
    }
    __syncthreads();
    float* rs_s = (float*)(sm1 + OFF_WT + 4096);
    float* mu_s = rs_s + 64;
    if (tid < 64){
        float s = 0.f, q = 0.f;
        #pragma unroll
        for (int w = 0; w < 8; w++){ s += sred[w*64 + tid]; q += ssqred[w*64 + tid]; }
        float mu = s * (1.f/256.f);
        float var = q * (1.f/256.f) - mu*mu;
        rs_s[tid] = rsqrtf(var + 1e-5f);
        mu_s[tid] = mu;
    }
    __syncthreads();

    // ---- normalize readback (L2-hot), write final, pooled partials ----
    float* pool  = (float*)(sm1 + OFF_WT + 4608);
    float* poolb = pool + 2048;
    {
        const int r = tid >> 2, dq = tid & 3;
        const float mu = mu_s[r], rs = rs_s[r];
        float* row = g_stacked + ((size_t)(pbase + r)*NF + f)*Dm + dq*64;
        #pragma unroll 4
        for (int j4 = 0; j4 < 64; j4 += 4){
            float4 yv = *(float4*)(row + j4);
            float v0 = rs*yv.x, v1 = rs*yv.y, v2 = rs*yv.z, v3 = rs*yv.w;
            v0 += __shfl_xor_sync(0xffffffffu, v0, 4);
            v1 += __shfl_xor_sync(0xffffffffu, v1, 4);
            v2 += __shfl_xor_sync(0xffffffffu, v2, 4);
            v3 += __shfl_xor_sync(0xffffffffu, v3, 4);
            v0 += __shfl_xor_sync(0xffffffffu, v0, 8);
            v1 += __shfl_xor_sync(0xffffffffu, v1, 8);
            v2 += __shfl_xor_sync(0xffffffffu, v2, 8);
            v3 += __shfl_xor_sync(0xffffffffu, v3, 8);
            v0 += __shfl_xor_sync(0xffffffffu, v0, 16);
            v1 += __shfl_xor_sync(0xffffffffu, v1, 16);
            v2 += __shfl_xor_sync(0xffffffffu, v2, 16);
            v3 += __shfl_xor_sync(0xffffffffu, v3, 16);
            if ((lane >> 2) == 0){
                float4 pv; pv.x = v0; pv.y = v1; pv.z = v2; pv.w = v3;
                *(float4*)(pool + wid*256 + dq*64 + j4) = pv;
            }
            const int dg = dq*64 + j4;
            float4 o;
            o.x = fmaf((yv.x - mu)*rs, lng_s[dg+0], lnb_s[dg+0]);
            o.y = fmaf((yv.y - mu)*rs, lng_s[dg+1], lnb_s[dg+1]);
            o.z = fmaf((yv.z - mu)*rs, lng_s[dg+2], lnb_s[dg+2]);
            o.w = fmaf((yv.w - mu)*rs, lng_s[dg+3], lnb_s[dg+3]);
            *(float4*)(row + j4) = o;
        }
    }
    // poolb: sum rows rs*mu
    if (tid < 64){
        float v = rs_s[tid]*mu_s[tid];
        v += __shfl_xor_sync(0xffffffffu, v, 1);
        v += __shfl_xor_sync(0xffffffffu, v, 2);
        v += __shfl_xor_sync(0xffffffffu, v, 4);
        v += __shfl_xor_sync(0xffffffffu, v, 8);
        v += __shfl_xor_sync(0xffffffffu, v, 16);
        if (lane == 0) poolb[wid] = v;
    }
    __syncthreads();
    {
        float sA = 0.f;
        #pragma unroll
        for (int w = 0; w < 8; w++) sA += pool[w*256 + tid];
        atomicAdd(&g_pooledA[((size_t)b*NF + f)*Dm + tid], sA);
        if (tid == 0) atomicAdd(&g_pooledB[b*NF + f], poolb[0] + poolb[1]);
    }
}

// ---------------------------------------------------------------------------
// K3 / Pass 2: weight GRN + softmax, split-K over features (unchanged, R5).
// ---------------------------------------------------------------------------
__global__ void __launch_bounds__(256,1) vsn_pass2(
    const float* __restrict__ lng,const float* __restrict__ lnb,
    const float* __restrict__ W1, const float* __restrict__ B1,
    const float* __restrict__ W2, const float* __restrict__ B2,
    const float* __restrict__ Wg, const float* __restrict__ Bg,
    const float* __restrict__ Ws, const float* __restrict__ Bs,
    const float* __restrict__ LNg,const float* __restrict__ LNb,
    float* wout)
{
    __shared__ float fp_s[256][16];
    __shared__ float pb_s[16];
    __shared__ float hw_s[Dm];
    __shared__ float part2[8][NF], part3[8][NF];
    __shared__ int s_last;

    const int f = blockIdx.x, tid = threadIdx.x;
    const float invT = 1.f/(float)Tt;

    if (tid < 16) pb_s[tid] = g_pooledB[tid*NF + f];
    __syncthreads();

    {
        const float lg = lng[f*Dm + tid], lb = lnb[f*Dm + tid];
        #pragma unroll
        for (int b = 0; b < 16; b++){
            float pa = g_pooledA[((size_t)b*NF + f)*Dm + tid];
            fp_s[tid][b] = fmaf(lg*(pa - pb_s[b]), invT, lb);
        }
    }
    __syncthreads();

    {
        float acc[16];
        #pragma unroll
        for (int b = 0; b < 16; b++) acc[b] = 0.f;
        const float* w1p = W1 + (size_t)f*256*Dm + tid;
        #pragma unroll 4
        for (int j = 0; j < 256; j++){
            float w = w1p[(size_t)j*Dm];
            const float4* fv = (const float4*)fp_s[j];
            float4 f0 = fv[0], f1 = fv[1], f2 = fv[2], f3 = fv[3];
            acc[0]  = fmaf(f0.x, w, acc[0]);  acc[1]  = fmaf(f0.y, w, acc[1]);
            acc[2]  = fmaf(f0.z, w, acc[2]);  acc[3]  = fmaf(f0.w, w, acc[3]);
            acc[4]  = fmaf(f1.x, w, acc[4]);  acc[5]  = fmaf(f1.y, w, acc[5]);
            acc[6]  = fmaf(f1.z, w, acc[6]);  acc[7]  = fmaf(f1.w, w, acc[7]);
            acc[8]  = fmaf(f2.x, w, acc[8]);  acc[9]  = fmaf(f2.y, w, acc[9]);
            acc[10] = fmaf(f2.z, w, acc[10]); acc[11] = fmaf(f2.w, w, acc[11]);
            acc[12] = fmaf(f3.x, w, acc[12]); acc[13] = fmaf(f3.y, w, acc[13]);
            acc[14] = fmaf(f3.z, w, acc[14]); acc[15] = fmaf(f3.w, w, acc[15]);
        }
        #pragma unroll
        for (int b = 0; b < 16; b++)
            atomicAdd(&g_h1[b*Dm + tid], acc[b]);
    }

    {
        const int k = tid & 31, bg2 = tid >> 5;
        float a0 = 0.f, a1 = 0.f;
        const float* wsp = Ws + (size_t)f*256*NF + k;
        #pragma unroll 4
        for (int j = 0; j < 256; j++){
            float w = wsp[(size_t)j*NF];
            a0 = fmaf(fp_s[j][bg2],   w, a0);
            a1 = fmaf(fp_s[j][bg2+8], w, a1);
        }
        atomicAdd(&g_sk[bg2*NF + k], a0);
        atomicAdd(&g_sk[(bg2+8)*NF + k], a1);
    }

    __threadfence();
    __syncthreads();
    if (tid == 0) s_last = (atomicAdd(&g_cnt, 1) == 31) ? 1 : 0;
    __syncthreads();
    if (!s_last) return;
    __threadfence();

    for (int b = 0; b < 16; b++){
        hw_s[tid] = eluf(__ldcg(&g_h1[b*Dm + tid]) + B1[tid]);
        __syncthreads();
        {
            const int k = tid & 31, pt = tid >> 5;
            float a2 = 0.f, a3 = 0.f;
            const int d0 = pt*32;
            #pragma unroll
            for (int d = d0; d < d0 + 32; d++){
                float h = hw_s[d];
                a2 = fmaf(h, W2[d*NF + k], a2);
                a3 = fmaf(h, Wg[d*NF + k], a3);
            }
            part2[pt][k] = a2; part3[pt][k] = a3;
        }
        __syncthreads();
        if (tid < 32){
            const int k = tid;
            float pw = B2[k], gw = Bg[k];
            #pragma unroll
            for (int p = 0; p < 8; p++){ pw += part2[p][k]; gw += part3[p][k]; }
            float sk = __ldcg(&g_sk[b*NF + k]) + Bs[k];
            float v = sk + sigf(gw) * pw;
            float s = v, ssq = v*v;
            #pragma unroll
            for (int o = 16; o > 0; o >>= 1){
                s   += __shfl_xor_sync(0xffffffffu, s, o);
                ssq += __shfl_xor_sync(0xffffffffu, ssq, o);
            }
            float mu = s * (1.f/32.f);
            float var = ssq * (1.f/32.f) - mu*mu;
            float y = fmaf((v - mu) * rsqrtf(var + 1e-5f), LNg[k], LNb[k]);
            float mx = y;
            #pragma unroll
            for (int o = 16; o > 0; o >>= 1) mx = fmaxf(mx, __shfl_xor_sync(0xffffffffu, mx, o));
            float e = expf(y - mx);
            float se = e;
            #pragma unroll
            for (int o = 16; o > 0; o >>= 1) se += __shfl_xor_sync(0xffffffffu, se, o);
            float w = e / se;
            g_weights[b*NF + k] = w;
            if (wout) wout[b*NF + k] = w;
        }
        __syncthreads();
    }
}

// ---------------------------------------------------------------------------
// K4 / Pass 3: selected = einsum(stacked, weights) — DRAM-roofline.
// ---------------------------------------------------------------------------
__global__ void __launch_bounds__(256,1) vsn_pass3(float* __restrict__ out)
{
    __shared__ float w_s[NF];
    const int p = blockIdx.x;
    const int b = p >> 9;
    const int tid = threadIdx.x;
    if (tid < NF) w_s[tid] = g_weights[b*NF + tid];
    __syncthreads();
    const float* base = g_stacked + (size_t)p*NF*Dm + tid;
    float acc = 0.f;
    #pragma unroll
    for (int f2 = 0; f2 < NF; f2++)
        acc = fmaf(base[(size_t)f2*Dm], w_s[f2], acc);
    out[(size_t)p*Dm + tid] = acc;
}

// ---------------------------------------------------------------------------
extern "C" void kernel_launch(void* const* d_in, const int* in_sizes, int n_in,
                              void* d_out, int out_size)
{
    const float* x   = (const float*)d_in[0];
    const float* w1  = (const float*)d_in[1];
    const float* b1  = (const float*)d_in[2];
    const float* w2  = (const float*)d_in[3];
    const float* b2  = (const float*)d_in[4];
    const float* wg  = (const float*)d_in[5];
    const float* bg  = (const float*)d_in[6];
    const float* ws  = (const float*)d_in[7];
    const float* bs  = (const float*)d_in[8];
    const float* lng = (const float*)d_in[9];
    const float* lnb = (const float*)d_in[10];
    const float* W1  = (const float*)d_in[11];
    const float* B1  = (const float*)d_in[12];
    const float* W2  = (const float*)d_in[13];
    const float* B2  = (const float*)d_in[14];
    const float* Wg  = (const float*)d_in[15];
    const float* Bg  = (const float*)d_in[16];
    const float* Ws  = (const float*)d_in[17];
    const float* Bs  = (const float*)d_in[18];
    const float* LNg = (const float*)d_in[19];
    const float* LNb = (const float*)d_in[20];

    cudaFuncSetAttribute(vsn_pass1, cudaFuncAttributeMaxDynamicSharedMemorySize, SMEM1_BYTES);

    float* out = (float*)d_out;
    float* wout = (out_size > BT*Dm) ? out + (size_t)BT*Dm : nullptr;

    vsn_prep<<<130, 256>>>(w2, wg);
    dim3 g1(NF, BT/MT);
    vsn_pass1<<<g1, 256, SMEM1_BYTES>>>(x, w1, b1, b2, bg, ws, bs, lng, lnb);
    vsn_pass2<<<32, 256>>>(lng, lnb, W1, B1, W2, B2, Wg, Bg, Ws, Bs, LNg, LNb, wout);
    vsn_pass3<<<BT, 256>>>(out);
}

// round 7
// speedup vs baseline: 3.8265x; 1.3548x over previous
#include <cuda_runtime.h>
#include <cuda_bf16.h>
#include <math.h>
#include <stdint.h>

#define NF 32
#define Dm 256
#define Hh 128
#define Bb 16
#define Tt 512
#define BT (Bb*Tt)      // 8192 positions
#define MT 64           // positions per CTA in pass1
#define PW 136          // bf16 pitch (elems) of prepped weight / h tiles
#define PWB 272         // bytes

// ---------------- scratch (device globals; no runtime allocation) ----------
__device__ float g_stacked[(size_t)BT*NF*Dm];   // 268 MB pre-LN y (B,T,F,D)
__device__ float g_rs[(size_t)BT*NF];           // per (p,f) 1/std
__device__ float g_mu[(size_t)BT*NF];           // per (p,f) mean
__device__ float g_pooledA[Bb*NF*Dm];           // sum_t rs_t * y[t,d]
__device__ float g_pooledB[Bb*NF];              // sum_t rs_t * mu_t
__device__ float g_weights[Bb*NF];
__device__ float g_h1[Bb*Dm];                   // split-K partials of fp@W1
__device__ float g_sk[Bb*NF];                   // split-K partials of fp@Ws
__device__ int   g_cnt;
// prepped weights: 128 parts (f*4 + t*2 + hilo), each [256 d][136 k] bf16
__device__ uint4 g_wprep4[128 * 4352];          // 8.9 MB

// ---------------- helpers --------------------------------------------------
__device__ __forceinline__ uint32_t smem_u32(const void* p){
    uint32_t a;
    asm("{ .reg .u64 t; cvta.to.shared.u64 t, %1; cvt.u32.u64 %0, t; }" : "=r"(a) : "l"(p));
    return a;
}
__device__ __forceinline__ void ldsm_x4(uint32_t (&r)[4], uint32_t a){
    asm volatile("ldmatrix.sync.aligned.m8n8.x4.shared.b16 {%0,%1,%2,%3}, [%4];"
        : "=r"(r[0]),"=r"(r[1]),"=r"(r[2]),"=r"(r[3]) : "r"(a));
}
__device__ __forceinline__ void ldsm_x2(uint32_t (&r)[2], uint32_t a){
    asm volatile("ldmatrix.sync.aligned.m8n8.x2.shared.b16 {%0,%1}, [%2];"
        : "=r"(r[0]),"=r"(r[1]) : "r"(a));
}
__device__ __forceinline__ void mma16816(float* c, const uint32_t (&a)[4], const uint32_t (&b)[2]){
    asm volatile("mma.sync.aligned.m16n8k16.row.col.f32.bf16.bf16.f32 "
        "{%0,%1,%2,%3}, {%4,%5,%6,%7}, {%8,%9}, {%0,%1,%2,%3};"
        : "+f"(c[0]),"+f"(c[1]),"+f"(c[2]),"+f"(c[3])
        : "r"(a[0]),"r"(a[1]),"r"(a[2]),"r"(a[3]), "r"(b[0]),"r"(b[1]));
}
#define CP16(d,s)    asm volatile("cp.async.cg.shared.global [%0], [%1], 16;" :: "r"(d), "l"(s) : "memory")
#define CP_COMMIT()  asm volatile("cp.async.commit_group;" ::: "memory")
#define CP_WAIT(n)   asm volatile("cp.async.wait_group %0;" :: "n"(n) : "memory")

__device__ __forceinline__ float eluf(float z){ return z > 0.f ? z : expm1f(z); }
__device__ __forceinline__ float sigf(float z){ return __fdividef(1.f, 1.f + __expf(-z)); }

// ---------------------------------------------------------------------------
// K1: prep (w2/wg -> bf16 hi/lo transposed pitch-136 images) + zero scratch.
// grid = 130: blocks 0..127 prep, 128..129 zero.
// ---------------------------------------------------------------------------
__global__ void __launch_bounds__(256,1) vsn_prep(const float* __restrict__ w2,
                                                  const float* __restrict__ wg)
{
    __shared__ float ts[128][65];
    const int bid = blockIdx.x;
    const int tid = threadIdx.x;

    if (bid >= 128){
        int z = bid - 128;
        for (int i = z*65536 + tid; i < z*65536 + 65536; i += 256) g_pooledA[i] = 0.f;
        if (z == 0){
            for (int i = tid; i < Bb*Dm; i += 256) g_h1[i] = 0.f;
            for (int i = tid; i < Bb*NF; i += 256){ g_sk[i] = 0.f; g_pooledB[i] = 0.f; }
            if (tid == 0) g_cnt = 0;
        }
        return;
    }

    const int f = bid >> 2, t = (bid >> 1) & 1, p = bid & 1;
    const float* W = (t ? wg : w2) + (size_t)f*Hh*Dm;                  // [k][d]
    __nv_bfloat16* dst = (__nv_bfloat16*)(g_wprep4 + (size_t)bid*4352); // [d][k pitch 136]

    for (int dc = 0; dc < 4; dc++){
        #pragma unroll
        for (int i = 0; i < 32; i++){
            int e = tid + i*256;
            int d = e & 63, k = e >> 6;
            ts[k][d] = W[(size_t)k*Dm + dc*64 + d];
        }
        __syncthreads();
        #pragma unroll
        for (int i = 0; i < 4; i++){
            int g = tid + i*256;
            int d = g >> 4, kg = g & 15;
            union { __nv_bfloat16 h[8]; uint4 v; } o;
            #pragma unroll
            for (int j = 0; j < 8; j++){
                float v = ts[kg*8 + j][d];
                __nv_bfloat16 hi = __float2bfloat16(v);
                o.h[j] = p ? __float2bfloat16(v - __bfloat162float(hi)) : hi;
            }
            *(uint4*)(dst + (size_t)(dc*64 + d)*PW + kg*8) = o.v;
        }
        __syncthreads();
    }
}

// ---------------------------------------------------------------------------
// K2 / Pass 1: HMMA bf16 3-term split, cp.async double-buffered weights,
// 2 CTAs/SM. Writes pre-LN y + per-row rs/mu. No normalize, no pooling.
// grid = (NF, BT/MT) = (32,128), 256 threads, 111872 B dyn smem.
// Warp = (q = wid&3 -> 8 d-cols, half = wid>>2 -> 32 rows).
// ---------------------------------------------------------------------------
#define OFF_HHI 0
#define OFF_HLO 17408
#define OFF_WT  34816           // 2 bufs x 4 parts x 8704 = 69632
#define OFF_B2  104448
#define OFF_BG  105472
#define OFF_WS  106496
#define OFF_BS  107520
#define OFF_W1  108544
#define OFF_B1  109056
#define OFF_X   109568
#define OFF_SRED 109824         // [4][64] f32
#define OFF_SSQ  110848         // [4][64] f32
#define SMEM1_BYTES 111872

extern __shared__ char sm1[];

__global__ void __launch_bounds__(256,2) vsn_pass1(
    const float* __restrict__ x,  const float* __restrict__ w1, const float* __restrict__ b1,
    const float* __restrict__ b2, const float* __restrict__ bg,
    const float* __restrict__ ws, const float* __restrict__ bs)
{
    const int f     = blockIdx.x;
    const int pbase = blockIdx.y * MT;
    const int tid   = threadIdx.x;
    const int lane  = tid & 31;
    const int wid   = tid >> 5;
    const int q     = wid & 3;
    const int half  = wid >> 2;

    char* HHI = sm1 + OFF_HHI;
    char* HLO = sm1 + OFF_HLO;
    float* b2_s = (float*)(sm1 + OFF_B2);
    float* bg_s = (float*)(sm1 + OFF_BG);
    float* ws_s = (float*)(sm1 + OFF_WS);
    float* bs_s = (float*)(sm1 + OFF_BS);
    float* w1_s = (float*)(sm1 + OFF_W1);
    float* b1_s = (float*)(sm1 + OFF_B1);
    float* x_s  = (float*)(sm1 + OFF_X);

    // ---- stage params ----
    b2_s[tid] = b2[f*Dm + tid];
    bg_s[tid] = bg[f*Dm + tid];
    ws_s[tid] = ws[f*Dm + tid];
    bs_s[tid] = bs[f*Dm + tid];
    if (tid < 128){ w1_s[tid] = w1[f*Hh + tid]; b1_s[tid] = b1[f*Hh + tid]; }
    if (tid < 64)  x_s[tid] = x[(size_t)(pbase + tid)*NF + f];
    __syncthreads();

    // ---- h split into bf16 hi/lo rows (row r = tid>>2, k-span (tid&3)*32) ----
    {
        const int r = tid >> 2, k0 = (tid & 3)*32;
        const float x_r = x_s[r];
        #pragma unroll
        for (int j = 0; j < 32; j += 2){
            float v0 = eluf(fmaf(x_r, w1_s[k0+j],   b1_s[k0+j]));
            float v1 = eluf(fmaf(x_r, w1_s[k0+j+1], b1_s[k0+j+1]));
            union { __nv_bfloat16 h[2]; uint32_t u; } hi, lo;
            hi.h[0] = __float2bfloat16(v0);
            hi.h[1] = __float2bfloat16(v1);
            lo.h[0] = __float2bfloat16(v0 - __bfloat162float(hi.h[0]));
            lo.h[1] = __float2bfloat16(v1 - __bfloat162float(hi.h[1]));
            *(uint32_t*)(HHI + r*PWB + (k0+j)*2) = hi.u;
            *(uint32_t*)(HLO + r*PWB + (k0+j)*2) = lo.u;
        }
    }

    const uint32_t sb  = smem_u32(sm1);
    const uint32_t aHI = sb + OFF_HHI, aLO = sb + OFF_HLO, wtb = sb + OFF_WT;
    const uint32_t a_off = (uint32_t)(((lane & 7) + 8*((lane>>3)&1)) * PWB + ((lane>>4)&1)*16);
    const uint32_t b_off = (uint32_t)((q*8 + (lane & 7)) * PWB + ((lane>>3)&1)*16);
    const char* wsrc = (const char*)g_wprep4 + (size_t)f*4*69632;

    auto stage = [&](int c){
        const uint32_t dstb = wtb + (c & 1)*34816;
        const char* srcc = wsrc + (size_t)c*8704;
        #pragma unroll
        for (int p4 = 0; p4 < 4; p4++){
            const char* src = srcc + (size_t)p4*69632;
            const uint32_t dst = dstb + p4*8704;
            CP16(dst + tid*16,        src + (size_t)tid*16);
            CP16(dst + (256+tid)*16,  src + (size_t)(256+tid)*16);
            if (tid < 32) CP16(dst + (512+tid)*16, src + (size_t)(512+tid)*16);
        }
    };

    float srow[4], ssqrow[4];
    #pragma unroll
    for (int i = 0; i < 4; i++){ srow[i] = 0.f; ssqrow[i] = 0.f; }

    stage(0); CP_COMMIT();

    for (int c = 0; c < 8; c++){
        if (c + 1 < 8){ stage(c + 1); CP_COMMIT(); CP_WAIT(1); }
        else          { CP_WAIT(0); }
        __syncthreads();   // buf (c&1) ready; also orders h/param writes on c=0

        const uint32_t wb = wtb + (c & 1)*34816;
        float accp[8], accg[8];
        #pragma unroll
        for (int i = 0; i < 8; i++){ accp[i] = 0.f; accg[i] = 0.f; }

        #pragma unroll 2
        for (int kk = 0; kk < 8; kk++){
            uint32_t Bph[2], Bpl[2], Bgh[2], Bgl[2];
            const uint32_t bb = b_off + kk*32;
            ldsm_x2(Bph, wb + bb);
            ldsm_x2(Bpl, wb + 8704  + bb);
            ldsm_x2(Bgh, wb + 17408 + bb);
            ldsm_x2(Bgl, wb + 26112 + bb);
            #pragma unroll
            for (int mt = 0; mt < 2; mt++){
                uint32_t Ah[4], Al[4];
                const uint32_t aa = (uint32_t)((half*32 + mt*16)*PWB) + a_off + kk*32;
                ldsm_x4(Ah, aHI + aa);
                ldsm_x4(Al, aLO + aa);
                mma16816(accp + mt*4, Ah, Bph);
                mma16816(accp + mt*4, Ah, Bpl);
                mma16816(accp + mt*4, Al, Bph);
                mma16816(accg + mt*4, Ah, Bgh);
                mma16816(accg + mt*4, Ah, Bgl);
                mma16816(accg + mt*4, Al, Bgh);
            }
        }

        // ---- epilogue: y pre-LN -> gmem, running stats ----
        {
            const int dg0 = c*32 + q*8 + (lane & 3)*2;
            #pragma unroll
            for (int mt = 0; mt < 2; mt++)
                #pragma unroll
                for (int hf = 0; hf < 2; hf++){
                    const int m = half*32 + mt*16 + (lane>>2) + 8*hf;
                    const float xm = x_s[m];
                    float p0 = accp[mt*4 + hf*2 + 0] + b2_s[dg0];
                    float p1 = accp[mt*4 + hf*2 + 1] + b2_s[dg0+1];
                    float g0 = sigf(accg[mt*4 + hf*2 + 0] + bg_s[dg0]);
                    float g1 = sigf(accg[mt*4 + hf*2 + 1] + bg_s[dg0+1]);
                    float y0 = fmaf(xm, ws_s[dg0],   bs_s[dg0])   + g0*p0;
                    float y1 = fmaf(xm, ws_s[dg0+1], bs_s[dg0+1]) + g1*p1;
                    float2 yy; yy.x = y0; yy.y = y1;
                    *(float2*)(g_stacked + ((size_t)(pbase + m)*NF + f)*Dm + dg0) = yy;
                    srow[mt*2 + hf] += y0 + y1;
                    ssqrow[mt*2 + hf] = fmaf(y0, y0, fmaf(y1, y1, ssqrow[mt*2 + hf]));
                }
        }
        __syncthreads();   // all warps done with buf (c&1) before it is restaged
    }

    // ---- LN stats -> g_rs / g_mu ----
    float* sred   = (float*)(sm1 + OFF_SRED);
    float* ssqred = (float*)(sm1 + OFF_SSQ);
    #pragma unroll
    for (int i = 0; i < 4; i++){
        float v = srow[i], w2v = ssqrow[i];
        v += __shfl_xor_sync(0xffffffffu, v, 1);  w2v += __shfl_xor_sync(0xffffffffu, w2v, 1);
        v += __shfl_xor_sync(0xffffffffu, v, 2);  w2v += __shfl_xor_sync(0xffffffffu, w2v, 2);
        if ((lane & 3) == 0){
            const int m = half*32 + (i>>1)*16 + (lane>>2) + 8*(i & 1);
            sred[q*64 + m]   = v;
            ssqred[q*64 + m] = w2v;
        }
    }
    __syncthreads();
    if (tid < 64){
        float s = sred[tid] + sred[64+tid] + sred[128+tid] + sred[192+tid];
        float sq = ssqred[tid] + ssqred[64+tid] + ssqred[128+tid] + ssqred[192+tid];
        float mu = s * (1.f/256.f);
        float var = sq * (1.f/256.f) - mu*mu;
        g_rs[(size_t)(pbase + tid)*NF + f] = rsqrtf(var + 1e-5f);
        g_mu[(size_t)(pbase + tid)*NF + f] = mu;
    }
}

// ---------------------------------------------------------------------------
// K3 / pool: pooledA[b,f,d] = sum_t rs*y ; pooledB[b,f] = sum_t rs*mu.
// grid = (NF, 128), 256 threads (thread = d). DRAM-rate read of y.
// ---------------------------------------------------------------------------
__global__ void __launch_bounds__(256,4) vsn_pool()
{
    __shared__ float rs_s[64], mu_s[64];
    const int f = blockIdx.x, pbase = blockIdx.y * 64, b = pbase >> 9;
    const int tid = threadIdx.x;
    if (tid < 64){
        rs_s[tid] = g_rs[(size_t)(pbase + tid)*NF + f];
        mu_s[tid] = g_mu[(size_t)(pbase + tid)*NF + f];
    }
    __syncthreads();
    const float* yp = g_stacked + ((size_t)pbase*NF + f)*Dm + tid;
    float acc = 0.f;
    #pragma unroll 8
    for (int i = 0; i < 64; i++)
        acc = fmaf(rs_s[i], yp[(size_t)i*NF*Dm], acc);
    atomicAdd(&g_pooledA[((size_t)b*NF + f)*Dm + tid], acc);
    if (tid < 64){
        float v = rs_s[tid]*mu_s[tid];
        v += __shfl_xor_sync(0xffffffffu, v, 1);
        v += __shfl_xor_sync(0xffffffffu, v, 2);
        v += __shfl_xor_sync(0xffffffffu, v, 4);
        v += __shfl_xor_sync(0xffffffffu, v, 8);
        v += __shfl_xor_sync(0xffffffffu, v, 16);
        if ((tid & 31) == 0) atomicAdd(&g_pooledB[b*NF + f], v);
    }
}

// ---------------------------------------------------------------------------
// K4 / Pass 2: weight GRN + softmax, split-K over features (R5 design).
// ---------------------------------------------------------------------------
__global__ void __launch_bounds__(256,1) vsn_pass2(
    const float* __restrict__ lng,const float* __restrict__ lnb,
    const float* __restrict__ W1, const float* __restrict__ B1,
    const float* __restrict__ W2, const float* __restrict__ B2,
    const float* __restrict__ Wg, const float* __restrict__ Bg,
    const float* __restrict__ Ws, const float* __restrict__ Bs,
    const float* __restrict__ LNg,const float* __restrict__ LNb,
    float* wout)
{
    __shared__ float fp_s[256][16];
    __shared__ float pb_s[16];
    __shared__ float hw_s[Dm];
    __shared__ float part2[8][NF], part3[8][NF];
    __shared__ int s_last;

    const int f = blockIdx.x, tid = threadIdx.x;
    const float invT = 1.f/(float)Tt;

    if (tid < 16) pb_s[tid] = g_pooledB[tid*NF + f];
    __syncthreads();

    {
        const float lg = lng[f*Dm + tid], lb = lnb[f*Dm + tid];
        #pragma unroll
        for (int b = 0; b < 16; b++){
            float pa = g_pooledA[((size_t)b*NF + f)*Dm + tid];
            fp_s[tid][b] = fmaf(lg*(pa - pb_s[b]), invT, lb);
        }
    }
    __syncthreads();

    {
        float acc[16];
        #pragma unroll
        for (int b = 0; b < 16; b++) acc[b] = 0.f;
        const float* w1p = W1 + (size_t)f*256*Dm + tid;
        #pragma unroll 4
        for (int j = 0; j < 256; j++){
            float w = w1p[(size_t)j*Dm];
            const float4* fv = (const float4*)fp_s[j];
            float4 f0 = fv[0], f1 = fv[1], f2 = fv[2], f3 = fv[3];
            acc[0]  = fmaf(f0.x, w, acc[0]);  acc[1]  = fmaf(f0.y, w, acc[1]);
            acc[2]  = fmaf(f0.z, w, acc[2]);  acc[3]  = fmaf(f0.w, w, acc[3]);
            acc[4]  = fmaf(f1.x, w, acc[4]);  acc[5]  = fmaf(f1.y, w, acc[5]);
            acc[6]  = fmaf(f1.z, w, acc[6]);  acc[7]  = fmaf(f1.w, w, acc[7]);
            acc[8]  = fmaf(f2.x, w, acc[8]);  acc[9]  = fmaf(f2.y, w, acc[9]);
            acc[10] = fmaf(f2.z, w, acc[10]); acc[11] = fmaf(f2.w, w, acc[11]);
            acc[12] = fmaf(f3.x, w, acc[12]); acc[13] = fmaf(f3.y, w, acc[13]);
            acc[14] = fmaf(f3.z, w, acc[14]); acc[15] = fmaf(f3.w, w, acc[15]);
        }
        #pragma unroll
        for (int b = 0; b < 16; b++)
            atomicAdd(&g_h1[b*Dm + tid], acc[b]);
    }

    {
        const int k = tid & 31, bg2 = tid >> 5;
        float a0 = 0.f, a1 = 0.f;
        const float* wsp = Ws + (size_t)f*256*NF + k;
        #pragma unroll 4
        for (int j = 0; j < 256; j++){
            float w = wsp[(size_t)j*NF];
            a0 = fmaf(fp_s[j][bg2],   w, a0);
            a1 = fmaf(fp_s[j][bg2+8], w, a1);
        }
        atomicAdd(&g_sk[bg2*NF + k], a0);
        atomicAdd(&g_sk[(bg2+8)*NF + k], a1);
    }

    __threadfence();
    __syncthreads();
    if (tid == 0) s_last = (atomicAdd(&g_cnt, 1) == 31) ? 1 : 0;
    __syncthreads();
    if (!s_last) return;
    __threadfence();

    for (int b = 0; b < 16; b++){
        hw_s[tid] = eluf(__ldcg(&g_h1[b*Dm + tid]) + B1[tid]);
        __syncthreads();
        {
            const int k = tid & 31, pt = tid >> 5;
            float a2 = 0.f, a3 = 0.f;
            const int d0 = pt*32;
            #pragma unroll
            for (int d = d0; d < d0 + 32; d++){
                float h = hw_s[d];
                a2 = fmaf(h, W2[d*NF + k], a2);
                a3 = fmaf(h, Wg[d*NF + k], a3);
            }
            part2[pt][k] = a2; part3[pt][k] = a3;
        }
        __syncthreads();
        if (tid < 32){
            const int k = tid;
            float pw = B2[k], gw = Bg[k];
            #pragma unroll
            for (int p = 0; p < 8; p++){ pw += part2[p][k]; gw += part3[p][k]; }
            float sk = __ldcg(&g_sk[b*NF + k]) + Bs[k];
            float v = sk + sigf(gw) * pw;
            float s = v, ssq = v*v;
            #pragma unroll
            for (int o = 16; o > 0; o >>= 1){
                s   += __shfl_xor_sync(0xffffffffu, s, o);
                ssq += __shfl_xor_sync(0xffffffffu, ssq, o);
            }
            float mu = s * (1.f/32.f);
            float var = ssq * (1.f/32.f) - mu*mu;
            float y = fmaf((v - mu) * rsqrtf(var + 1e-5f), LNg[k], LNb[k]);
            float mx = y;
            #pragma unroll
            for (int o = 16; o > 0; o >>= 1) mx = fmaxf(mx, __shfl_xor_sync(0xffffffffu, mx, o));
            float e = expf(y - mx);
            float se = e;
            #pragma unroll
            for (int o = 16; o > 0; o >>= 1) se += __shfl_xor_sync(0xffffffffu, se, o);
            float w = e / se;
            g_weights[b*NF + k] = w;
            if (wout) wout[b*NF + k] = w;
        }
        __syncthreads();
    }
}

// ---------------------------------------------------------------------------
// K5 / Pass 3: fused LN + weighted combine.
// out[p,d] = sum_f w[b,f]*(lng[f,d]*(y-mu)*rs + lnb[f,d])
// grid = BT/8 = 1024 CTAs, 256 threads (thread = d), 8 positions per CTA.
// ---------------------------------------------------------------------------
__global__ void __launch_bounds__(256,1) vsn_pass3(
    const float* __restrict__ lng, const float* __restrict__ lnb,
    float* __restrict__ out)
{
    __shared__ float A_s[8][NF], D_s[8][NF], w_s[NF];
    const int p0 = blockIdx.x * 8;
    const int b  = p0 >> 9;
    const int tid = threadIdx.x;

    if (tid < NF) w_s[tid] = g_weights[b*NF + tid];
    __syncthreads();
    {
        const int i = tid >> 5, f2 = tid & 31;
        float rsv = g_rs[(size_t)(p0 + i)*NF + f2];
        float muv = g_mu[(size_t)(p0 + i)*NF + f2];
        float a = w_s[f2] * rsv;
        A_s[i][f2] = a;
        D_s[i][f2] = a * muv;
    }
    float lngr[NF];
    float bias = 0.f;
    #pragma unroll
    for (int f2 = 0; f2 < NF; f2++){
        lngr[f2] = lng[f2*Dm + tid];
        bias = fmaf(lnb[f2*Dm + tid], w_s[f2], bias);
    }
    __syncthreads();

    #pragma unroll
    for (int i = 0; i < 8; i++){
        const float* yrow = g_stacked + ((size_t)(p0 + i)*NF)*Dm + tid;
        float acc = bias;
        #pragma unroll
        for (int f2 = 0; f2 < NF; f2++){
            float y = yrow[(size_t)f2*Dm];
            float t = fmaf(y, A_s[i][f2], -D_s[i][f2]);
            acc = fmaf(lngr[f2], t, acc);
        }
        out[(size_t)(p0 + i)*Dm + tid] = acc;
    }
}

// ---------------------------------------------------------------------------
extern "C" void kernel_launch(void* const* d_in, const int* in_sizes, int n_in,
                              void* d_out, int out_size)
{
    const float* x   = (const float*)d_in[0];
    const float* w1  = (const float*)d_in[1];
    const float* b1  = (const float*)d_in[2];
    const float* w2  = (const float*)d_in[3];
    const float* b2  = (const float*)d_in[4];
    const float* wg  = (const float*)d_in[5];
    const float* bg  = (const float*)d_in[6];
    const float* ws  = (const float*)d_in[7];
    const float* bs  = (const float*)d_in[8];
    const float* lng = (const float*)d_in[9];
    const float* lnb = (const float*)d_in[10];
    const float* W1  = (const float*)d_in[11];
    const float* B1  = (const float*)d_in[12];
    const float* W2  = (const float*)d_in[13];
    const float* B2  = (const float*)d_in[14];
    const float* Wg  = (const float*)d_in[15];
    const float* Bg  = (const float*)d_in[16];
    const float* Ws  = (const float*)d_in[17];
    const float* Bs  = (const float*)d_in[18];
    const float* LNg = (const float*)d_in[19];
    const float* LNb = (const float*)d_in[20];

    cudaFuncSetAttribute(vsn_pass1, cudaFuncAttributeMaxDynamicSharedMemorySize, SMEM1_BYTES);

    float* out = (float*)d_out;
    float* wout = (out_size > BT*Dm) ? out + (size_t)BT*Dm : nullptr;

    vsn_prep<<<130, 256>>>(w2, wg);
    dim3 g1(NF, BT/MT);
    vsn_pass1<<<g1, 256, SMEM1_BYTES>>>(x, w1, b1, b2, bg, ws, bs);
    dim3 gp(NF, 128);
    vsn_pool<<<gp, 256>>>();
    vsn_pass2<<<32, 256>>>(lng, lnb, W1, B1, W2, B2, Wg, Bg, Ws, Bs, LNg, LNb, wout);
    vsn_pass3<<<1024, 256>>>(lng, lnb, out);
}

// round 8
// speedup vs baseline: 4.4016x; 1.1503x over previous
#include <cuda_runtime.h>
#include <cuda_bf16.h>
#include <math.h>
#include <stdint.h>

#define NF 32
#define Dm 256
#define Hh 128
#define Bb 16
#define Tt 512
#define BT (Bb*Tt)      // 8192 positions
#define MT 128          // positions per CTA in pass1
#define PW 136          // bf16 pitch (elems) of prepped weight / h tiles
#define PWB 272         // bytes

// ---------------- scratch (device globals; no runtime allocation) ----------
__device__ float g_stacked[(size_t)BT*NF*Dm];   // 268 MB pre-LN y (B,T,F,D)
__device__ float g_rs[(size_t)BT*NF];           // per (p,f) 1/std
__device__ float g_mu[(size_t)BT*NF];           // per (p,f) mean
__device__ float g_pooledA[Bb*NF*Dm];           // sum_t rs_t * y[t,d]
__device__ float g_pooledB[Bb*NF];              // sum_t rs_t * mu_t
__device__ float g_weights[Bb*NF];
__device__ float g_h1[Bb*Dm];                   // split-K partials of fp@W1
__device__ float g_sk[Bb*NF];                   // split-K partials of fp@Ws
__device__ int   g_cnt;
// prepped weights: 128 parts (f*4 + t*2 + hilo), each [256 d][136 k] bf16
__device__ uint4 g_wprep4[128 * 4352];          // 8.9 MB

// ---------------- helpers --------------------------------------------------
__device__ __forceinline__ uint32_t smem_u32(const void* p){
    uint32_t a;
    asm("{ .reg .u64 t; cvta.to.shared.u64 t, %1; cvt.u32.u64 %0, t; }" : "=r"(a) : "l"(p));
    return a;
}
__device__ __forceinline__ void ldsm_x4(uint32_t (&r)[4], uint32_t a){
    asm volatile("ldmatrix.sync.aligned.m8n8.x4.shared.b16 {%0,%1,%2,%3}, [%4];"
        : "=r"(r[0]),"=r"(r[1]),"=r"(r[2]),"=r"(r[3]) : "r"(a));
}
__device__ __forceinline__ void ldsm_x2(uint32_t (&r)[2], uint32_t a){
    asm volatile("ldmatrix.sync.aligned.m8n8.x2.shared.b16 {%0,%1}, [%2];"
        : "=r"(r[0]),"=r"(r[1]) : "r"(a));
}
__device__ __forceinline__ void mma16816(float* c, const uint32_t (&a)[4], const uint32_t (&b)[2]){
    asm volatile("mma.sync.aligned.m16n8k16.row.col.f32.bf16.bf16.f32 "
        "{%0,%1,%2,%3}, {%4,%5,%6,%7}, {%8,%9}, {%0,%1,%2,%3};"
        : "+f"(c[0]),"+f"(c[1]),"+f"(c[2]),"+f"(c[3])
        : "r"(a[0]),"r"(a[1]),"r"(a[2]),"r"(a[3]), "r"(b[0]),"r"(b[1]));
}
#define CP16(d,s)    asm volatile("cp.async.cg.shared.global [%0], [%1], 16;" :: "r"(d), "l"(s) : "memory")
#define CP_COMMIT()  asm volatile("cp.async.commit_group;" ::: "memory")
#define CP_WAIT(n)   asm volatile("cp.async.wait_group %0;" :: "n"(n) : "memory")

__device__ __forceinline__ float eluf(float z){ return z > 0.f ? z : expm1f(z); }
__device__ __forceinline__ float sigf(float z){ return __fdividef(1.f, 1.f + __expf(-z)); }

// ---------------------------------------------------------------------------
// K1: prep (w2/wg -> bf16 hi/lo transposed pitch-136 images) + zero scratch.
// grid = 130: blocks 0..127 prep, 128..129 zero.
// ---------------------------------------------------------------------------
__global__ void __launch_bounds__(256,1) vsn_prep(const float* __restrict__ w2,
                                                  const float* __restrict__ wg)
{
    __shared__ float ts[128][65];
    const int bid = blockIdx.x;
    const int tid = threadIdx.x;

    if (bid >= 128){
        int z = bid - 128;
        for (int i = z*65536 + tid; i < z*65536 + 65536; i += 256) g_pooledA[i] = 0.f;
        if (z == 0){
            for (int i = tid; i < Bb*Dm; i += 256) g_h1[i] = 0.f;
            for (int i = tid; i < Bb*NF; i += 256){ g_sk[i] = 0.f; g_pooledB[i] = 0.f; }
            if (tid == 0) g_cnt = 0;
        }
        return;
    }

    const int f = bid >> 2, t = (bid >> 1) & 1, p = bid & 1;
    const float* W = (t ? wg : w2) + (size_t)f*Hh*Dm;                   // [k][d]
    __nv_bfloat16* dst = (__nv_bfloat16*)(g_wprep4 + (size_t)bid*4352); // [d][k pitch 136]

    for (int dc = 0; dc < 4; dc++){
        #pragma unroll
        for (int i = 0; i < 32; i++){
            int e = tid + i*256;
            int d = e & 63, k = e >> 6;
            ts[k][d] = W[(size_t)k*Dm + dc*64 + d];
        }
        __syncthreads();
        #pragma unroll
        for (int i = 0; i < 4; i++){
            int g = tid + i*256;
            int d = g >> 4, kg = g & 15;
            union { __nv_bfloat16 h[8]; uint4 v; } o;
            #pragma unroll
            for (int j = 0; j < 8; j++){
                float v = ts[kg*8 + j][d];
                __nv_bfloat16 hi = __float2bfloat16(v);
                o.h[j] = p ? __float2bfloat16(v - __bfloat162float(hi)) : hi;
            }
            *(uint4*)(dst + (size_t)(dc*64 + d)*PW + kg*8) = o.v;
        }
        __syncthreads();
    }
}

// ---------------------------------------------------------------------------
// K2 / Pass 1: HMMA bf16 3-term split, MT=128 positions/CTA, 2 CTAs/SM.
// Single-buffered weight chunks (DC=32); cross-CTA overlap hides staging.
// grid = (NF, BT/MT) = (32,64), 256 threads, 110080 B dyn smem.
// Warp = (q = wid&3 -> 8 d-cols, half = wid>>2 -> 64 rows), 4 m-tiles/warp.
// ---------------------------------------------------------------------------
#define OFF_HHI 0
#define OFF_HLO 34816
#define OFF_WT  69632           // 4 parts x 8704 = 34816 (single buffer)
#define OFF_B2  104448
#define OFF_BG  105472
#define OFF_WS  106496
#define OFF_BS  107520
#define OFF_W1  108544
#define OFF_B1  109056
#define OFF_X   109568
#define SMEM1_BYTES 110080
// stats overlay (after last chunk): sred = OFF_WT [4][128], ssq = OFF_WT+2048

extern __shared__ char sm1[];

__global__ void __launch_bounds__(256,2) vsn_pass1(
    const float* __restrict__ x,  const float* __restrict__ w1, const float* __restrict__ b1,
    const float* __restrict__ b2, const float* __restrict__ bg,
    const float* __restrict__ ws, const float* __restrict__ bs)
{
    const int f     = blockIdx.x;
    const int pbase = blockIdx.y * MT;
    const int tid   = threadIdx.x;
    const int lane  = tid & 31;
    const int wid   = tid >> 5;
    const int q     = wid & 3;
    const int half  = wid >> 2;

    char* HHI = sm1 + OFF_HHI;      // [128][272 B] bf16 hi
    char* HLO = sm1 + OFF_HLO;
    float* b2_s = (float*)(sm1 + OFF_B2);
    float* bg_s = (float*)(sm1 + OFF_BG);
    float* ws_s = (float*)(sm1 + OFF_WS);
    float* bs_s = (float*)(sm1 + OFF_BS);
    float* w1_s = (float*)(sm1 + OFF_W1);
    float* b1_s = (float*)(sm1 + OFF_B1);
    float* x_s  = (float*)(sm1 + OFF_X);

    // ---- stage params ----
    b2_s[tid] = b2[f*Dm + tid];
    bg_s[tid] = bg[f*Dm + tid];
    ws_s[tid] = ws[f*Dm + tid];
    bs_s[tid] = bs[f*Dm + tid];
    if (tid < 128){ w1_s[tid] = w1[f*Hh + tid]; b1_s[tid] = b1[f*Hh + tid]; }
    if (tid < 128) x_s[tid] = x[(size_t)(pbase + tid)*NF + f];
    __syncthreads();

    // ---- h split into bf16 hi/lo rows (row r = tid>>1, k-half (tid&1)*64) ----
    {
        const int r = tid >> 1, k0 = (tid & 1)*64;
        const float x_r = x_s[r];
        #pragma unroll
        for (int j = 0; j < 64; j += 2){
            float v0 = eluf(fmaf(x_r, w1_s[k0+j],   b1_s[k0+j]));
            float v1 = eluf(fmaf(x_r, w1_s[k0+j+1], b1_s[k0+j+1]));
            union { __nv_bfloat16 h[2]; uint32_t u; } hi, lo;
            hi.h[0] = __float2bfloat16(v0);
            hi.h[1] = __float2bfloat16(v1);
            lo.h[0] = __float2bfloat16(v0 - __bfloat162float(hi.h[0]));
            lo.h[1] = __float2bfloat16(v1 - __bfloat162float(hi.h[1]));
            *(uint32_t*)(HHI + r*PWB + (k0+j)*2) = hi.u;
            *(uint32_t*)(HLO + r*PWB + (k0+j)*2) = lo.u;
        }
    }

    const uint32_t sb  = smem_u32(sm1);
    const uint32_t aHI = sb + OFF_HHI, aLO = sb + OFF_HLO, wtb = sb + OFF_WT;
    const uint32_t a_off = (uint32_t)(((lane & 7) + 8*((lane>>3)&1)) * PWB + ((lane>>4)&1)*16);
    const uint32_t b_off = (uint32_t)((q*8 + (lane & 7)) * PWB + ((lane>>3)&1)*16);
    const char* wsrc = (const char*)g_wprep4 + (size_t)f*4*69632;

    float srow[8], ssqrow[8];
    #pragma unroll
    for (int i = 0; i < 8; i++){ srow[i] = 0.f; ssqrow[i] = 0.f; }

    for (int c = 0; c < 8; c++){
        // ---- stage weight chunk c: 4 parts x 32 rows x 272 B (cp.async) ----
        {
            const char* srcc = wsrc + (size_t)c*8704;
            #pragma unroll
            for (int p4 = 0; p4 < 4; p4++){
                const char* src = srcc + (size_t)p4*69632;
                const uint32_t dst = wtb + p4*8704;
                CP16(dst + tid*16,       src + (size_t)tid*16);
                CP16(dst + (256+tid)*16, src + (size_t)(256+tid)*16);
                if (tid < 32) CP16(dst + (512+tid)*16, src + (size_t)(512+tid)*16);
            }
        }
        CP_COMMIT(); CP_WAIT(0);
        __syncthreads();   // buf ready (also orders h/param writes on c=0)

        float accp[16], accg[16];
        #pragma unroll
        for (int i = 0; i < 16; i++){ accp[i] = 0.f; accg[i] = 0.f; }

        #pragma unroll 2
        for (int kk = 0; kk < 8; kk++){
            uint32_t Bph[2], Bpl[2], Bgh[2], Bgl[2];
            const uint32_t bb = b_off + kk*32;
            ldsm_x2(Bph, wtb + bb);
            ldsm_x2(Bpl, wtb + 8704  + bb);
            ldsm_x2(Bgh, wtb + 17408 + bb);
            ldsm_x2(Bgl, wtb + 26112 + bb);
            #pragma unroll
            for (int mt = 0; mt < 4; mt++){
                uint32_t Ah[4], Al[4];
                const uint32_t aa = (uint32_t)((half*64 + mt*16)*PWB) + a_off + kk*32;
                ldsm_x4(Ah, aHI + aa);
                ldsm_x4(Al, aLO + aa);
                mma16816(accp + mt*4, Ah, Bph);
                mma16816(accp + mt*4, Ah, Bpl);
                mma16816(accp + mt*4, Al, Bph);
                mma16816(accg + mt*4, Ah, Bgh);
                mma16816(accg + mt*4, Ah, Bgl);
                mma16816(accg + mt*4, Al, Bgh);
            }
        }

        // ---- epilogue: y pre-LN -> gmem, running stats ----
        {
            const int dg0 = c*32 + q*8 + (lane & 3)*2;
            #pragma unroll
            for (int mt = 0; mt < 4; mt++)
                #pragma unroll
                for (int hf = 0; hf < 2; hf++){
                    const int m = half*64 + mt*16 + (lane>>2) + 8*hf;
                    const float xm = x_s[m];
                    float p0 = accp[mt*4 + hf*2 + 0] + b2_s[dg0];
                    float p1 = accp[mt*4 + hf*2 + 1] + b2_s[dg0+1];
                    float g0 = sigf(accg[mt*4 + hf*2 + 0] + bg_s[dg0]);
                    float g1 = sigf(accg[mt*4 + hf*2 + 1] + bg_s[dg0+1]);
                    float y0 = fmaf(xm, ws_s[dg0],   bs_s[dg0])   + g0*p0;
                    float y1 = fmaf(xm, ws_s[dg0+1], bs_s[dg0+1]) + g1*p1;
                    float2 yy; yy.x = y0; yy.y = y1;
                    *(float2*)(g_stacked + ((size_t)(pbase + m)*NF + f)*Dm + dg0) = yy;
                    srow[mt*2 + hf] += y0 + y1;
                    ssqrow[mt*2 + hf] = fmaf(y0, y0, fmaf(y1, y1, ssqrow[mt*2 + hf]));
                }
        }
        __syncthreads();   // all warps done reading buf before restage
    }

    // ---- LN stats -> g_rs / g_mu (weight buffer overlay now free) ----
    float* sred   = (float*)(sm1 + OFF_WT);
    float* ssqred = sred + 512;
    #pragma unroll
    for (int i = 0; i < 8; i++){
        float v = srow[i], w2v = ssqrow[i];
        v += __shfl_xor_sync(0xffffffffu, v, 1);  w2v += __shfl_xor_sync(0xffffffffu, w2v, 1);
        v += __shfl_xor_sync(0xffffffffu, v, 2);  w2v += __shfl_xor_sync(0xffffffffu, w2v, 2);
        if ((lane & 3) == 0){
            const int m = half*64 + (i>>1)*16 + (lane>>2) + 8*(i & 1);
            sred[q*128 + m]   = v;
            ssqred[q*128 + m] = w2v;
        }
    }
    __syncthreads();
    if (tid < 128){
        float s  = sred[tid] + sred[128+tid] + sred[256+tid] + sred[384+tid];
        float sq = ssqred[tid] + ssqred[128+tid] + ssqred[256+tid] + ssqred[384+tid];
        float mu = s * (1.f/256.f);
        float var = sq * (1.f/256.f) - mu*mu;
        g_rs[(size_t)(pbase + tid)*NF + f] = rsqrtf(var + 1e-5f);
        g_mu[(size_t)(pbase + tid)*NF + f] = mu;
    }
}

// ---------------------------------------------------------------------------
// K3 / pool: pooledA[b,f,d] = sum_t rs*y ; pooledB[b,f] = sum_t rs*mu.
// grid = (NF, 128), 256 threads (thread = d). DRAM-rate read of y.
// ---------------------------------------------------------------------------
__global__ void __launch_bounds__(256,4) vsn_pool()
{
    __shared__ float rs_s[64], mu_s[64];
    const int f = blockIdx.x, pbase = blockIdx.y * 64, b = pbase >> 9;
    const int tid = threadIdx.x;
    if (tid < 64){
        rs_s[tid] = g_rs[(size_t)(pbase + tid)*NF + f];
        mu_s[tid] = g_mu[(size_t)(pbase + tid)*NF + f];
    }
    __syncthreads();
    const float* yp = g_stacked + ((size_t)pbase*NF + f)*Dm + tid;
    float acc = 0.f;
    #pragma unroll 8
    for (int i = 0; i < 64; i++)
        acc = fmaf(rs_s[i], yp[(size_t)i*NF*Dm], acc);
    atomicAdd(&g_pooledA[((size_t)b*NF + f)*Dm + tid], acc);
    if (tid < 64){
        float v = rs_s[tid]*mu_s[tid];
        v += __shfl_xor_sync(0xffffffffu, v, 1);
        v += __shfl_xor_sync(0xffffffffu, v, 2);
        v += __shfl_xor_sync(0xffffffffu, v, 4);
        v += __shfl_xor_sync(0xffffffffu, v, 8);
        v += __shfl_xor_sync(0xffffffffu, v, 16);
        if ((tid & 31) == 0) atomicAdd(&g_pooledB[b*NF + f], v);
    }
}

// ---------------------------------------------------------------------------
// K4 / Pass 2: weight GRN + softmax, split-K x4 per feature.
// grid = 128 (f*4 + slice of 64 W1/Ws rows), 256 threads.
// Last CTA finalizes: elu, W2/Wg GEMVs, LN, softmax.
// ---------------------------------------------------------------------------
__global__ void __launch_bounds__(256,1) vsn_pass2(
    const float* __restrict__ lng,const float* __restrict__ lnb,
    const float* __restrict__ W1, const float* __restrict__ B1,
    const float* __restrict__ W2, const float* __restrict__ B2,
    const float* __restrict__ Wg, const float* __restrict__ Bg,
    const float* __restrict__ Ws, const float* __restrict__ Bs,
    const float* __restrict__ LNg,const float* __restrict__ LNb,
    float* wout)
{
    __shared__ float fp_s[64][16];
    __shared__ float pb_s[16];
    __shared__ float hw_s[Dm];
    __shared__ float part2[8][NF], part3[8][NF];
    __shared__ int s_last;

    const int f = blockIdx.x >> 2, slice = blockIdx.x & 3;
    const int j0 = slice * 64;
    const int tid = threadIdx.x;
    const float invT = 1.f/(float)Tt;

    if (tid < 16) pb_s[tid] = g_pooledB[tid*NF + f];
    __syncthreads();

    // fp[j][b] for this slice's 64 rows
    {
        const int j = tid & 63, b4 = tid >> 6;
        const float lg = lng[f*Dm + j0 + j], lb = lnb[f*Dm + j0 + j];
        #pragma unroll
        for (int bb = 0; bb < 4; bb++){
            int b = b4*4 + bb;
            float pa = g_pooledA[((size_t)b*NF + f)*Dm + j0 + j];
            fp_s[j][b] = fmaf(lg*(pa - pb_s[b]), invT, lb);
        }
    }
    __syncthreads();

    // split-K: contribution to hw_pre[b][d] (d = tid)
    {
        float acc[16];
        #pragma unroll
        for (int b = 0; b < 16; b++) acc[b] = 0.f;
        const float* w1p = W1 + (size_t)(f*256 + j0)*Dm + tid;
        #pragma unroll 4
        for (int j = 0; j < 64; j++){
            float w = w1p[(size_t)j*Dm];
            const float4* fv = (const float4*)fp_s[j];
            float4 f0 = fv[0], f1 = fv[1], f2 = fv[2], f3 = fv[3];
            acc[0]  = fmaf(f0.x, w, acc[0]);  acc[1]  = fmaf(f0.y, w, acc[1]);
            acc[2]  = fmaf(f0.z, w, acc[2]);  acc[3]  = fmaf(f0.w, w, acc[3]);
            acc[4]  = fmaf(f1.x, w, acc[4]);  acc[5]  = fmaf(f1.y, w, acc[5]);
            acc[6]  = fmaf(f1.z, w, acc[6]);  acc[7]  = fmaf(f1.w, w, acc[7]);
            acc[8]  = fmaf(f2.x, w, acc[8]);  acc[9]  = fmaf(f2.y, w, acc[9]);
            acc[10] = fmaf(f2.z, w, acc[10]); acc[11] = fmaf(f2.w, w, acc[11]);
            acc[12] = fmaf(f3.x, w, acc[12]); acc[13] = fmaf(f3.y, w, acc[13]);
            acc[14] = fmaf(f3.z, w, acc[14]); acc[15] = fmaf(f3.w, w, acc[15]);
        }
        #pragma unroll
        for (int b = 0; b < 16; b++)
            atomicAdd(&g_h1[b*Dm + tid], acc[b]);
    }

    // split-K skip: sk[b][k]
    {
        const int k = tid & 31, bg2 = tid >> 5;
        float a0 = 0.f, a1 = 0.f;
        const float* wsp = Ws + (size_t)(f*256 + j0)*NF + k;
        #pragma unroll 4
        for (int j = 0; j < 64; j++){
            float w = wsp[(size_t)j*NF];
            a0 = fmaf(fp_s[j][bg2],   w, a0);
            a1 = fmaf(fp_s[j][bg2+8], w, a1);
        }
        atomicAdd(&g_sk[bg2*NF + k], a0);
        atomicAdd(&g_sk[(bg2+8)*NF + k], a1);
    }

    __threadfence();
    __syncthreads();
    if (tid == 0) s_last = (atomicAdd(&g_cnt, 1) == 127) ? 1 : 0;
    __syncthreads();
    if (!s_last) return;
    __threadfence();

    for (int b = 0; b < 16; b++){
        hw_s[tid] = eluf(__ldcg(&g_h1[b*Dm + tid]) + B1[tid]);
        __syncthreads();
        {
            const int k = tid & 31, pt = tid >> 5;
            float a2 = 0.f, a3 = 0.f;
            const int d0 = pt*32;
            #pragma unroll
            for (int d = d0; d < d0 + 32; d++){
                float h = hw_s[d];
                a2 = fmaf(h, W2[d*NF + k], a2);
                a3 = fmaf(h, Wg[d*NF + k], a3);
            }
            part2[pt][k] = a2; part3[pt][k] = a3;
        }
        __syncthreads();
        if (tid < 32){
            const int k = tid;
            float pw = B2[k], gw = Bg[k];
            #pragma unroll
            for (int p = 0; p < 8; p++){ pw += part2[p][k]; gw += part3[p][k]; }
            float sk = __ldcg(&g_sk[b*NF + k]) + Bs[k];
            float v = sk + sigf(gw) * pw;
            float s = v, ssq = v*v;
            #pragma unroll
            for (int o = 16; o > 0; o >>= 1){
                s   += __shfl_xor_sync(0xffffffffu, s, o);
                ssq += __shfl_xor_sync(0xffffffffu, ssq, o);
            }
            float mu = s * (1.f/32.f);
            float var = ssq * (1.f/32.f) - mu*mu;
            float y = fmaf((v - mu) * rsqrtf(var + 1e-5f), LNg[k], LNb[k]);
            float mx = y;
            #pragma unroll
            for (int o = 16; o > 0; o >>= 1) mx = fmaxf(mx, __shfl_xor_sync(0xffffffffu, mx, o));
            float e = expf(y - mx);
            float se = e;
            #pragma unroll
            for (int o = 16; o > 0; o >>= 1) se += __shfl_xor_sync(0xffffffffu, se, o);
            float w = e / se;
            g_weights[b*NF + k] = w;
            if (wout) wout[b*NF + k] = w;
        }
        __syncthreads();
    }
}

// ---------------------------------------------------------------------------
// K5 / Pass 3: fused LN + weighted combine (DRAM-roofline).
// ---------------------------------------------------------------------------
__global__ void __launch_bounds__(256,1) vsn_pass3(
    const float* __restrict__ lng, const float* __restrict__ lnb,
    float* __restrict__ out)
{
    __shared__ float A_s[8][NF], D_s[8][NF], w_s[NF];
    const int p0 = blockIdx.x * 8;
    const int b  = p0 >> 9;
    const int tid = threadIdx.x;

    if (tid < NF) w_s[tid] = g_weights[b*NF + tid];
    __syncthreads();
    {
        const int i = tid >> 5, f2 = tid & 31;
        float rsv = g_rs[(size_t)(p0 + i)*NF + f2];
        float muv = g_mu[(size_t)(p0 + i)*NF + f2];
        float a = w_s[f2] * rsv;
        A_s[i][f2] = a;
        D_s[i][f2] = a * muv;
    }
    float lngr[NF];
    float bias = 0.f;
    #pragma unroll
    for (int f2 = 0; f2 < NF; f2++){
        lngr[f2] = lng[f2*Dm + tid];
        bias = fmaf(lnb[f2*Dm + tid], w_s[f2], bias);
    }
    __syncthreads();

    #pragma unroll
    for (int i = 0; i < 8; i++){
        const float* yrow = g_stacked + ((size_t)(p0 + i)*NF)*Dm + tid;
        float acc = bias;
        #pragma unroll
        for (int f2 = 0; f2 < NF; f2++){
            float y = yrow[(size_t)f2*Dm];
            float t = fmaf(y, A_s[i][f2], -D_s[i][f2]);
            acc = fmaf(lngr[f2], t, acc);
        }
        out[(size_t)(p0 + i)*Dm + tid] = acc;
    }
}

// ---------------------------------------------------------------------------
extern "C" void kernel_launch(void* const* d_in, const int* in_sizes, int n_in,
                              void* d_out, int out_size)
{
    const float* x   = (const float*)d_in[0];
    const float* w1  = (const float*)d_in[1];
    const float* b1  = (const float*)d_in[2];
    const float* w2  = (const float*)d_in[3];
    const float* b2  = (const float*)d_in[4];
    const float* wg  = (const float*)d_in[5];
    const float* bg  = (const float*)d_in[6];
    const float* ws  = (const float*)d_in[7];
    const float* bs  = (const float*)d_in[8];
    const float* lng = (const float*)d_in[9];
    const float* lnb = (const float*)d_in[10];
    const float* W1  = (const float*)d_in[11];
    const float* B1  = (const float*)d_in[12];
    const float* W2  = (const float*)d_in[13];
    const float* B2  = (const float*)d_in[14];
    const float* Wg  = (const float*)d_in[15];
    const float* Bg  = (const float*)d_in[16];
    const float* Ws  = (const float*)d_in[17];
    const float* Bs  = (const float*)d_in[18];
    const float* LNg = (const float*)d_in[19];
    const float* LNb = (const float*)d_in[20];

    cudaFuncSetAttribute(vsn_pass1, cudaFuncAttributeMaxDynamicSharedMemorySize, SMEM1_BYTES);

    float* out = (float*)d_out;
    float* wout = (out_size > BT*Dm) ? out + (size_t)BT*Dm : nullptr;

    vsn_prep<<<130, 256>>>(w2, wg);
    dim3 g1(NF, BT/MT);
    vsn_pass1<<<g1, 256, SMEM1_BYTES>>>(x, w1, b1, b2, bg, ws, bs);
    dim3 gp(NF, 128);
    vsn_pool<<<gp, 256>>>();
    vsn_pass2<<<128, 256>>>(lng, lnb, W1, B1, W2, B2, Wg, Bg, Ws, Bs, LNg, LNb, wout);
    vsn_pass3<<<1024, 256>>>(lng, lnb, out);
}